// round 8
// baseline (speedup 1.0000x reference)
#include <cuda_runtime.h>
#include <cuda_bf16.h>
#include <math.h>
#include <stdint.h>

// Problem constants
#define T0 512
#define TT 2048
#define WIDTH 2048
#define NH 16
#define KH 4
#define HD 128
#define KC_BASE (TT*WIDTH)
#define VC_BASE (KC_BASE + TT*KH*HD)
#define NEGV -2.3819763e38f

// Scratch
__device__ float g_qg[TT * NH * 256];
__device__ float g_kraw[TT * KH * HD];
__device__ float g_q[TT * NH * HD];
__device__ float g_enc[TT * NH * HD];

// ---------------------------------------------------------------------------
// helpers
// ---------------------------------------------------------------------------
__device__ __forceinline__ uint32_t f2tf(float f) {
    uint32_t r;
    asm("cvt.rna.tf32.f32 %0, %1;" : "=r"(r) : "f"(f));
    return r;
}

__device__ __forceinline__ uint32_t smem_u32(const void* p) {
    uint32_t a;
    asm("{ .reg .u64 t; cvta.to.shared.u64 t, %1; cvt.u32.u64 %0, t; }"
        : "=r"(a) : "l"(p));
    return a;
}

__device__ __forceinline__ void cpasync16(uint32_t s, const float* g) {
    asm volatile("cp.async.ca.shared.global [%0], [%1], 16;" :: "r"(s), "l"(g));
}

// m16n8k8 tf32 MMA, fp32 accumulate.
__device__ __forceinline__ void mma8(float* c, const uint32_t* a, const uint32_t* b) {
    asm volatile(
        "mma.sync.aligned.m16n8k8.row.col.f32.tf32.tf32.f32 "
        "{%0,%1,%2,%3},{%4,%5,%6,%7},{%8,%9},{%0,%1,%2,%3};"
        : "+f"(c[0]), "+f"(c[1]), "+f"(c[2]), "+f"(c[3])
        : "r"(a[0]), "r"(a[1]), "r"(a[2]), "r"(a[3]), "r"(b[0]), "r"(b[1]));
}

// ---------------------------------------------------------------------------
// cp.async pipelined tf32 GEMM core (unchanged).
// ---------------------------------------------------------------------------
#define ASTRF 20
#define BSTRF 136
#define A_STAGE (128 * ASTRF)
#define B_STAGE (16 * BSTRF)
#define STAGE_F (A_STAGE + B_STAGE)
#define GEMM_SMEM_BYTES (3 * STAGE_F * 4)

__device__ __forceinline__ void issue_stage(
    uint32_t sbase, int stage, const float* A, int lda,
    const float* B, int ldb, int k0, int tid)
{
    const uint32_t aS = sbase + stage * (STAGE_F * 4);
    const uint32_t bS = aS + A_STAGE * 4;
    const int ar = tid >> 2, ak = (tid & 3) * 4;
    const int br = tid >> 5, bc = (tid & 31) * 4;
    cpasync16(aS + (ar * ASTRF + ak) * 4,          A + (long)ar * lda + k0 + ak);
    cpasync16(aS + ((64 + ar) * ASTRF + ak) * 4,   A + (long)(64 + ar) * lda + k0 + ak);
    cpasync16(bS + (br * BSTRF + bc) * 4,          B + (long)(k0 + br) * ldb + bc);
    cpasync16(bS + ((8 + br) * BSTRF + bc) * 4,    B + (long)(k0 + 8 + br) * ldb + bc);
    asm volatile("cp.async.commit_group;" ::: "memory");
}

__device__ void gemm_async_core(
    const float* __restrict__ A, int lda,
    const float* __restrict__ B, int ldb,
    float* __restrict__ C, int ldc, int Kdim)
{
    extern __shared__ float smf[];
    const uint32_t sbase = smem_u32(smf);

    const int tid = threadIdx.x;
    const int lane = tid & 31;
    const int g = lane >> 2;
    const int t = lane & 3;
    const int wid = tid >> 5;
    const int mw = (wid >> 1) * 32;
    const int nw = (wid & 1) * 64;

    const int nt = Kdim / 16;

    issue_stage(sbase, 0, A, lda, B, ldb, 0, tid);
    issue_stage(sbase, 1, A, lda, B, ldb, 16, tid);

    float acc[2][8][4] = {};

    for (int kt = 0; kt < nt; kt++) {
        if (kt + 2 < nt) {
            issue_stage(sbase, (kt + 2) % 3, A, lda, B, ldb, (kt + 2) * 16, tid);
            asm volatile("cp.async.wait_group %0;" :: "n"(2) : "memory");
        } else if (kt + 1 < nt) {
            asm volatile("cp.async.wait_group %0;" :: "n"(1) : "memory");
        } else {
            asm volatile("cp.async.wait_group %0;" :: "n"(0) : "memory");
        }
        __syncthreads();

        const float* AsF = smf + (kt % 3) * STAGE_F;
        const float* BsF = AsF + A_STAGE;

        #pragma unroll
        for (int h = 0; h < 2; h++) {
            const int k0 = h * 8;
            uint32_t afr[2][4], bfr[8][2];
            #pragma unroll
            for (int tm = 0; tm < 2; tm++) {
                const int mb = mw + tm * 16;
                afr[tm][0] = f2tf(AsF[(mb + g)     * ASTRF + k0 + t]);
                afr[tm][1] = f2tf(AsF[(mb + g + 8) * ASTRF + k0 + t]);
                afr[tm][2] = f2tf(AsF[(mb + g)     * ASTRF + k0 + t + 4]);
                afr[tm][3] = f2tf(AsF[(mb + g + 8) * ASTRF + k0 + t + 4]);
            }
            #pragma unroll
            for (int tn = 0; tn < 8; tn++) {
                const int nb = nw + tn * 8 + g;
                bfr[tn][0] = f2tf(BsF[(k0 + t)     * BSTRF + nb]);
                bfr[tn][1] = f2tf(BsF[(k0 + t + 4) * BSTRF + nb]);
            }
            #pragma unroll
            for (int tm = 0; tm < 2; tm++)
                #pragma unroll
                for (int tn = 0; tn < 8; tn++)
                    mma8(acc[tm][tn], afr[tm], bfr[tn]);
        }
        __syncthreads();
    }

    #pragma unroll
    for (int tm = 0; tm < 2; tm++) {
        #pragma unroll
        for (int tn = 0; tn < 8; tn++) {
            const int r0 = mw + tm * 16 + g;
            const int cc = nw + tn * 8 + 2 * t;
            *(float2*)&C[r0 * ldc + cc]       = make_float2(acc[tm][tn][0], acc[tm][tn][1]);
            *(float2*)&C[(r0 + 8) * ldc + cc] = make_float2(acc[tm][tn][2], acc[tm][tn][3]);
        }
    }
}

// Fused projections: qg (y 0..31), K (y 32..35), V (y 36..39). grid (16, 40).
__global__ __launch_bounds__(256, 2) void proj_fused_kernel(
    const float* __restrict__ x0, const float* __restrict__ x1,
    const float* __restrict__ qgw0, const float* __restrict__ qgw1,
    const float* __restrict__ kw0, const float* __restrict__ kw1,
    const float* __restrict__ vw0, const float* __restrict__ vw1,
    float* __restrict__ qg, float* __restrict__ kraw, float* __restrict__ vcache)
{
    const int tile = blockIdx.x;
    const int y = blockIdx.y;
    const float* A = (tile < 4) ? (x0 + (long)tile * 128 * WIDTH)
                                : (x1 + (long)(tile - 4) * 128 * WIDTH);
    const float* B;
    float* C;
    int ldb, ldc;
    if (y < 32) {
        const int n = y >> 1, bn = (y & 1) * 128;
        B = ((tile < 4) ? qgw0 : qgw1) + (long)n * WIDTH * 256 + bn;
        ldb = 256;
        C = qg + (long)tile * 128 * (NH * 256) + n * 256 + bn;
        ldc = NH * 256;
    } else if (y < 36) {
        const int kk = y - 32;
        B = ((tile < 4) ? kw0 : kw1) + (long)kk * WIDTH * HD;
        ldb = HD;
        C = kraw + (long)tile * 128 * (KH * HD) + kk * HD;
        ldc = KH * HD;
    } else {
        const int kk = y - 36;
        B = ((tile < 4) ? vw0 : vw1) + (long)kk * WIDTH * HD;
        ldb = HD;
        C = vcache + (long)tile * 128 * (KH * HD) + kk * HD;
        ldc = KH * HD;
    }
    gemm_async_core(A, WIDTH, B, ldb, C, ldc, WIDTH);
}

// output projection: grid (16, 16)
__global__ __launch_bounds__(256, 2) void proj_out_kernel(
    const float* __restrict__ enc,
    const float* __restrict__ ow0, const float* __restrict__ ow1,
    float* __restrict__ out)
{
    const int tile = blockIdx.x;
    const int bn = blockIdx.y * 128;
    const float* A = enc + (long)tile * 128 * (NH * HD);
    const float* B = ((tile < 4) ? ow0 : ow1) + bn;
    float* C = out + (long)tile * 128 * WIDTH + bn;
    gemm_async_core(A, NH * HD, B, WIDTH, C, WIDTH, NH * HD);
}

// ---------------------------------------------------------------------------
// RMSNorm + RoPE
// ---------------------------------------------------------------------------
__global__ __launch_bounds__(128) void qnorm_rope(
    const float* __restrict__ qg, float* __restrict__ qout,
    const int* __restrict__ positions,
    const float* __restrict__ qn0, const float* __restrict__ qn1)
{
    int row  = blockIdx.x * 4 + (threadIdx.x >> 5);
    int lane = threadIdx.x & 31;
    int t = row >> 4;
    int n = row & 15;
    const float* src = qg + t * (NH * 256) + n * 256;

    float v0 = src[lane];
    float v1 = src[lane + 32];
    float v2 = src[lane + 64];
    float v3 = src[lane + 96];
    float ss = v0 * v0 + v1 * v1 + v2 * v2 + v3 * v3;
    #pragma unroll
    for (int o = 16; o; o >>= 1) ss += __shfl_xor_sync(0xffffffffu, ss, o);
    float inv = rsqrtf(ss * (1.0f / 128.0f) + 1e-6f);

    const float* qn = (t < T0) ? qn0 : qn1;
    v0 = v0 * inv * (1.0f + qn[lane]);
    v1 = v1 * inv * (1.0f + qn[lane + 32]);
    v2 = v2 * inv * (1.0f + qn[lane + 64]);
    v3 = v3 * inv * (1.0f + qn[lane + 96]);

    float p = (float)positions[t];
    float freq = powf(1000000.0f, -(float)lane / 32.0f);
    float s, c;
    sincosf(p * freq, &s, &c);

    const float SCL = 0.08838834764831845f;
    float* dst = qout + t * (NH * HD) + n * HD;
    dst[lane]      = (v0 * c - v1 * s) * SCL;
    dst[lane + 32] = (v1 * c + v0 * s) * SCL;
    dst[lane + 64] = v2 * SCL;
    dst[lane + 96] = v3 * SCL;
}

__global__ __launch_bounds__(128) void knorm_rope(
    const float* __restrict__ kraw, float* __restrict__ kcache,
    const int* __restrict__ positions,
    const float* __restrict__ kn0, const float* __restrict__ kn1)
{
    int row  = blockIdx.x * 4 + (threadIdx.x >> 5);
    int lane = threadIdx.x & 31;
    int t  = row >> 2;
    int kk = row & 3;
    const float* src = kraw + t * (KH * HD) + kk * HD;

    float v0 = src[lane];
    float v1 = src[lane + 32];
    float v2 = src[lane + 64];
    float v3 = src[lane + 96];
    float ss = v0 * v0 + v1 * v1 + v2 * v2 + v3 * v3;
    #pragma unroll
    for (int o = 16; o; o >>= 1) ss += __shfl_xor_sync(0xffffffffu, ss, o);
    float inv = rsqrtf(ss * (1.0f / 128.0f) + 1e-6f);

    const float* kn = (t < T0) ? kn0 : kn1;
    v0 = v0 * inv * (1.0f + kn[lane]);
    v1 = v1 * inv * (1.0f + kn[lane + 32]);
    v2 = v2 * inv * (1.0f + kn[lane + 64]);
    v3 = v3 * inv * (1.0f + kn[lane + 96]);

    float p = (float)positions[t];
    float freq = powf(1000000.0f, -(float)lane / 32.0f);
    float s, c;
    sincosf(p * freq, &s, &c);

    float* dst = kcache + t * (KH * HD) + kk * HD;
    dst[lane]      = v0 * c - v1 * s;
    dst[lane + 32] = v1 * c + v0 * s;
    dst[lane + 64] = v2;
    dst[lane + 96] = v3;
}

// ---------------------------------------------------------------------------
// Flash attention: 2 GQA heads x 64 queries per CTA, 512 threads (16 warps).
// S warp tile 16x32 (8 M-groups x 2 N-groups); PV warp tile 16x64.
// tf32 mma.sync, 3-slot rotating cp.async K/V pipeline.
// smem (floats): Q tf32 [128][132] | 3 x KV fp32 [64][132] | S [128][72]
// ---------------------------------------------------------------------------
#define QSTR 132
#define KVSTR 132
#define SSTR 72
#define SLOT_F (64 * KVSTR)
#define AQ_OFF 0
#define AKV_OFF (128 * QSTR)
#define AS_OFF (AKV_OFF + 3 * SLOT_F)
#define ATT_SMEM_F (AS_OFF + 128 * SSTR)

__device__ __forceinline__ void att_issue(
    uint32_t kvbase, int slot, const float* __restrict__ src, int sb, int tid)
{
    const uint32_t dst = kvbase + slot * (SLOT_F * 4);
    #pragma unroll
    for (int i = 0; i < 4; i++) {
        const int lin = tid + 512 * i;
        const int r = lin >> 5;
        const int c4 = (lin & 31) * 4;
        cpasync16(dst + (r * KVSTR + c4) * 4, src + (long)(sb + r) * (KH * HD) + c4);
    }
    asm volatile("cp.async.commit_group;" ::: "memory");
}

__global__ __launch_bounds__(512, 1) void attn_kernel(
    const float* __restrict__ q, const float* __restrict__ kc,
    const float* __restrict__ vc, const float* __restrict__ qg,
    float* __restrict__ enc)
{
    extern __shared__ float smf[];
    uint32_t* Qs = (uint32_t*)(smf + AQ_OFF);
    float*    Ss = smf + AS_OFF;
    const uint32_t kvbase = smem_u32(smf + AKV_OFF);
    __shared__ float m_s[128], l_s[128], a_s[128];

    const int tid = threadIdx.x;
    const int lane = tid & 31;
    const int g = lane >> 2;
    const int t = lane & 3;
    const int wid = tid >> 5;                 // 0..15
    const int mS = (wid >> 1) * 16;           // S/PV warp row base
    const int wnS = (wid & 1) * 32;           // S warp col base
    const int wnO = (wid & 1) * 64;           // PV warp col base
    const int qt = gridDim.x - 1 - blockIdx.x;   // heavy tiles first
    const int n0 = blockIdx.y * 2;               // head pair (same kvh)
    const int kvh = n0 >> 2;
    const int qbase = qt * 64;

    const float* kbase = kc + kvh * HD;
    const float* vbase = vc + kvh * HD;

    // preamble: kick off K(0), V(0); stage Q (tf32) for both heads
    att_issue(kvbase, 0, kbase, 0, tid);
    att_issue(kvbase, 1, vbase, 0, tid);
    for (int idx = tid; idx < 128 * 128; idx += 512) {
        int r = idx >> 7, c = idx & 127;
        int head = n0 + (r >> 6);
        int qrow = qbase + (r & 63);
        Qs[r * QSTR + c] = f2tf(q[qrow * (NH * HD) + head * HD + c]);
    }
    if (tid < 128) { m_s[tid] = -3.0e38f; l_s[tid] = 0.0f; }

    float accO[8][4] = {};   // PV: rows mS+g/(+8), cols wnO + tn*8 + 2t

    for (int j = 0; j <= qt; j++) {
        const int nsb = (j + 1 <= qt) ? (j + 1) * 64 : qt * 64;  // clamped prefetch

        // K(j) ready (V(j) may still be in flight)
        asm volatile("cp.async.wait_group %0;" :: "n"(1) : "memory");
        __syncthreads();

        // prefetch K(j+1) into slot freed by PV(j-1)
        att_issue(kvbase, (2 * j + 2) % 3, kbase, nsb, tid);

        // ---- S = Q K^T (128x64) from slot (2j)%3. Warp tile 16x32. ----
        const float* Kf = smf + AKV_OFF + ((2 * j) % 3) * SLOT_F;
        float sacc[4][4] = {};
        #pragma unroll
        for (int ks = 0; ks < 16; ks++) {
            const int k0 = ks * 8;
            uint32_t afr[4], bfr[4][2];
            afr[0] = Qs[(mS + g)     * QSTR + k0 + t];
            afr[1] = Qs[(mS + g + 8) * QSTR + k0 + t];
            afr[2] = Qs[(mS + g)     * QSTR + k0 + t + 4];
            afr[3] = Qs[(mS + g + 8) * QSTR + k0 + t + 4];
            #pragma unroll
            for (int tn = 0; tn < 4; tn++) {
                const int key = wnS + tn * 8 + g;
                bfr[tn][0] = f2tf(Kf[key * KVSTR + k0 + t]);
                bfr[tn][1] = f2tf(Kf[key * KVSTR + k0 + t + 4]);
            }
            #pragma unroll
            for (int tn = 0; tn < 4; tn++) mma8(sacc[tn], afr, bfr[tn]);
        }
        const bool diag = (j == qt);
        #pragma unroll
        for (int tn = 0; tn < 4; tn++) {
            const int cc = wnS + tn * 8 + 2 * t;
            const int r0 = mS + g, r1 = r0 + 8;
            const int q0 = r0 & 63, q1 = r1 & 63;   // query row within tile
            float v0 = sacc[tn][0], v1 = sacc[tn][1];
            float v2 = sacc[tn][2], v3 = sacc[tn][3];
            if (diag) {
                if (cc     > q0) v0 = NEGV;
                if (cc + 1 > q0) v1 = NEGV;
                if (cc     > q1) v2 = NEGV;
                if (cc + 1 > q1) v3 = NEGV;
            }
            Ss[r0 * SSTR + cc] = v0; Ss[r0 * SSTR + cc + 1] = v1;
            Ss[r1 * SSTR + cc] = v2; Ss[r1 * SSTR + cc + 1] = v3;
        }
        __syncthreads();   // S visible; K(j) slot now free

        // prefetch V(j+1) into K(j)'s slot
        att_issue(kvbase, (2 * j) % 3, vbase, nsb, tid);

        // V(j) ready
        asm volatile("cp.async.wait_group %0;" :: "n"(2) : "memory");
        __syncthreads();

        // ---- online softmax: 4 threads per row, 16 cols each ----
        {
            int r = tid >> 2;
            int qq = tid & 3;
            float* row = Ss + r * SSTR + qq * 16;
            float mold = m_s[r];
            float rmax = -3.0e38f;
            #pragma unroll
            for (int c = 0; c < 16; c++) rmax = fmaxf(rmax, row[c]);
            rmax = fmaxf(rmax, __shfl_xor_sync(0xffffffffu, rmax, 1));
            rmax = fmaxf(rmax, __shfl_xor_sync(0xffffffffu, rmax, 2));
            float mn = fmaxf(mold, rmax);
            float sum = 0.0f;
            #pragma unroll
            for (int c = 0; c < 16; c++) {
                float pv = __expf(row[c] - mn);
                sum += pv;
                row[c] = __uint_as_float(f2tf(pv));
            }
            sum += __shfl_xor_sync(0xffffffffu, sum, 1);
            sum += __shfl_xor_sync(0xffffffffu, sum, 2);
            if (qq == 0) {
                float al = __expf(mold - mn);
                l_s[r] = l_s[r] * al + sum;
                m_s[r] = mn;
                a_s[r] = al;
            }
        }
        __syncthreads();

        // ---- rescale + O += P V from slot (2j+1)%3. Warp tile 16x64. ----
        const float* Vf = smf + AKV_OFF + ((2 * j + 1) % 3) * SLOT_F;
        const float al0 = a_s[mS + g];
        const float al1 = a_s[mS + g + 8];
        #pragma unroll
        for (int tn = 0; tn < 8; tn++) {
            accO[tn][0] *= al0; accO[tn][1] *= al0;
            accO[tn][2] *= al1; accO[tn][3] *= al1;
        }
        const uint32_t* Ps = (const uint32_t*)Ss;
        #pragma unroll
        for (int ks = 0; ks < 8; ks++) {
            const int k0 = ks * 8;
            uint32_t afr[4], bfr[8][2];
            afr[0] = Ps[(mS + g)     * SSTR + k0 + t];
            afr[1] = Ps[(mS + g + 8) * SSTR + k0 + t];
            afr[2] = Ps[(mS + g)     * SSTR + k0 + t + 4];
            afr[3] = Ps[(mS + g + 8) * SSTR + k0 + t + 4];
            #pragma unroll
            for (int tn = 0; tn < 8; tn++) {
                const int hb = wnO + tn * 8 + g;
                bfr[tn][0] = f2tf(Vf[(k0 + t)     * KVSTR + hb]);
                bfr[tn][1] = f2tf(Vf[(k0 + t + 4) * KVSTR + hb]);
            }
            #pragma unroll
            for (int tn = 0; tn < 8; tn++) mma8(accO[tn], afr, bfr[tn]);
        }
    }

    asm volatile("cp.async.wait_group %0;" :: "n"(0) : "memory");

    // epilogue: 1/l scaling + fused sigmoid gate
    const int r0 = mS + g;
    const int r1 = r0 + 8;
    const int h0 = n0 + (r0 >> 6), h1 = n0 + (r1 >> 6);
    const int qr0 = qbase + (r0 & 63), qr1 = qbase + (r1 & 63);
    const float inv0 = 1.0f / l_s[r0];
    const float inv1 = 1.0f / l_s[r1];
    #pragma unroll
    for (int tn = 0; tn < 8; tn++) {
        const int cc = wnO + tn * 8 + 2 * t;
        float2 gg0 = *(const float2*)&qg[qr0 * (NH * 256) + h0 * 256 + 128 + cc];
        float2 gg1 = *(const float2*)&qg[qr1 * (NH * 256) + h1 * 256 + 128 + cc];
        float s00 = 1.0f / (1.0f + __expf(-gg0.x));
        float s01 = 1.0f / (1.0f + __expf(-gg0.y));
        float s10 = 1.0f / (1.0f + __expf(-gg1.x));
        float s11 = 1.0f / (1.0f + __expf(-gg1.y));
        float* d0 = enc + qr0 * (NH * HD) + h0 * HD + cc;
        float* d1 = enc + qr1 * (NH * HD) + h1 * HD + cc;
        *(float2*)d0 = make_float2(accO[tn][0] * inv0 * s00, accO[tn][1] * inv0 * s01);
        *(float2*)d1 = make_float2(accO[tn][2] * inv1 * s10, accO[tn][3] * inv1 * s11);
    }
}

// ---------------------------------------------------------------------------
extern "C" void kernel_launch(void* const* d_in, const int* in_sizes, int n_in,
                              void* d_out, int out_size)
{
    const float* x0    = (const float*)d_in[0];
    const float* x1    = (const float*)d_in[1];
    const int*   pos   = (const int*)d_in[2];
    const float* qg_w0 = (const float*)d_in[4];
    const float* k_w0  = (const float*)d_in[5];
    const float* v_w0  = (const float*)d_in[6];
    const float* qn0   = (const float*)d_in[7];
    const float* kn0   = (const float*)d_in[8];
    const float* o_w0  = (const float*)d_in[9];
    const float* qg_w1 = (const float*)d_in[10];
    const float* k_w1  = (const float*)d_in[11];
    const float* v_w1  = (const float*)d_in[12];
    const float* qn1   = (const float*)d_in[13];
    const float* kn1   = (const float*)d_in[14];
    const float* o_w1  = (const float*)d_in[15];

    float* out = (float*)d_out;

    float *qg, *kraw, *q, *enc;
    cudaGetSymbolAddress((void**)&qg,   g_qg);
    cudaGetSymbolAddress((void**)&kraw, g_kraw);
    cudaGetSymbolAddress((void**)&q,    g_q);
    cudaGetSymbolAddress((void**)&enc,  g_enc);

    cudaFuncSetAttribute(proj_fused_kernel, cudaFuncAttributeMaxDynamicSharedMemorySize, GEMM_SMEM_BYTES);
    cudaFuncSetAttribute(proj_out_kernel,   cudaFuncAttributeMaxDynamicSharedMemorySize, GEMM_SMEM_BYTES);
    cudaFuncSetAttribute(attn_kernel, cudaFuncAttributeMaxDynamicSharedMemorySize,
                         ATT_SMEM_F * sizeof(float));

    // all projections in one launch
    proj_fused_kernel<<<dim3(16, 40), 256, GEMM_SMEM_BYTES>>>(
        x0, x1, qg_w0, qg_w1, k_w0, k_w1, v_w0, v_w1, qg, kraw, out + VC_BASE);

    // norms + rope
    qnorm_rope<<<TT*NH/4, 128>>>(qg, q, pos, qn0, qn1);
    knorm_rope<<<TT*KH/4, 128>>>(kraw, out + KC_BASE, pos, kn0, kn1);

    // attention: 2 GQA heads per CTA, 512 threads, cp.async pipeline, fused gate
    attn_kernel<<<dim3(TT/64, NH/2), 512, ATT_SMEM_F * sizeof(float)>>>(
        q, out + KC_BASE, out + VC_BASE, qg, enc);

    // output projection
    proj_out_kernel<<<dim3(16, 16), 256, GEMM_SMEM_BYTES>>>(enc, o_w0, o_w1, out);
}

// round 9
// speedup vs baseline: 1.0005x; 1.0005x over previous
#include <cuda_runtime.h>
#include <cuda_bf16.h>
#include <math.h>
#include <stdint.h>

// Problem constants
#define T0 512
#define TT 2048
#define WIDTH 2048
#define NH 16
#define KH 4
#define HD 128
#define KC_BASE (TT*WIDTH)
#define VC_BASE (KC_BASE + TT*KH*HD)
#define NEGV -2.3819763e38f

// Scratch
__device__ float g_qg[TT * NH * 256];
__device__ float g_kraw[TT * KH * HD];
__device__ float g_q[TT * NH * HD];     // tf32-rounded q
__device__ float g_ktf[TT * KH * HD];   // tf32-rounded roped K
__device__ float g_vtf[TT * KH * HD];   // tf32-rounded V
__device__ float g_enc[TT * NH * HD];

// ---------------------------------------------------------------------------
// helpers
// ---------------------------------------------------------------------------
__device__ __forceinline__ uint32_t f2tf(float f) {
    uint32_t r;
    asm("cvt.rna.tf32.f32 %0, %1;" : "=r"(r) : "f"(f));
    return r;
}

__device__ __forceinline__ uint32_t smem_u32(const void* p) {
    uint32_t a;
    asm("{ .reg .u64 t; cvta.to.shared.u64 t, %1; cvt.u32.u64 %0, t; }"
        : "=r"(a) : "l"(p));
    return a;
}

__device__ __forceinline__ void cpasync16(uint32_t s, const float* g) {
    asm volatile("cp.async.ca.shared.global [%0], [%1], 16;" :: "r"(s), "l"(g));
}

// m16n8k8 tf32 MMA, fp32 accumulate.
__device__ __forceinline__ void mma8(float* c, const uint32_t* a, const uint32_t* b) {
    asm volatile(
        "mma.sync.aligned.m16n8k8.row.col.f32.tf32.tf32.f32 "
        "{%0,%1,%2,%3},{%4,%5,%6,%7},{%8,%9},{%0,%1,%2,%3};"
        : "+f"(c[0]), "+f"(c[1]), "+f"(c[2]), "+f"(c[3])
        : "r"(a[0]), "r"(a[1]), "r"(a[2]), "r"(a[3]), "r"(b[0]), "r"(b[1]));
}

// FMA-pipe exp (exp2 poly, |rel err| ~4e-5 << tf32 quantization).
__device__ __forceinline__ float exp_poly(float x) {
    float xl = x * 1.4426950408889634f;
    xl = fmaxf(fminf(xl, 125.0f), -125.0f);
    float nf = rintf(xl);
    float fr = xl - nf;
    float t = fmaf(0.0096183425f, fr, 0.055503327f);
    t = fmaf(t, fr, 0.24022651f);
    t = fmaf(t, fr, 0.69314718f);
    t = fmaf(t, fr, 1.0f);
    return __uint_as_float(__float_as_uint(t) + (int)nf * 8388608);
}

// ---------------------------------------------------------------------------
// cp.async pipelined tf32 GEMM core. Optional second (tf32-rounded) output.
// ---------------------------------------------------------------------------
#define ASTRF 20
#define BSTRF 136
#define A_STAGE (128 * ASTRF)
#define B_STAGE (16 * BSTRF)
#define STAGE_F (A_STAGE + B_STAGE)
#define GEMM_SMEM_BYTES (3 * STAGE_F * 4)

__device__ __forceinline__ void issue_stage(
    uint32_t sbase, int stage, const float* A, int lda,
    const float* B, int ldb, int k0, int tid)
{
    const uint32_t aS = sbase + stage * (STAGE_F * 4);
    const uint32_t bS = aS + A_STAGE * 4;
    const int ar = tid >> 2, ak = (tid & 3) * 4;
    const int br = tid >> 5, bc = (tid & 31) * 4;
    cpasync16(aS + (ar * ASTRF + ak) * 4,          A + (long)ar * lda + k0 + ak);
    cpasync16(aS + ((64 + ar) * ASTRF + ak) * 4,   A + (long)(64 + ar) * lda + k0 + ak);
    cpasync16(bS + (br * BSTRF + bc) * 4,          B + (long)(k0 + br) * ldb + bc);
    cpasync16(bS + ((8 + br) * BSTRF + bc) * 4,    B + (long)(k0 + 8 + br) * ldb + bc);
    asm volatile("cp.async.commit_group;" ::: "memory");
}

__device__ void gemm_async_core(
    const float* __restrict__ A, int lda,
    const float* __restrict__ B, int ldb,
    float* __restrict__ C, float* __restrict__ C2, int ldc, int Kdim)
{
    extern __shared__ float smf[];
    const uint32_t sbase = smem_u32(smf);

    const int tid = threadIdx.x;
    const int lane = tid & 31;
    const int g = lane >> 2;
    const int t = lane & 3;
    const int wid = tid >> 5;
    const int mw = (wid >> 1) * 32;
    const int nw = (wid & 1) * 64;

    const int nt = Kdim / 16;

    issue_stage(sbase, 0, A, lda, B, ldb, 0, tid);
    issue_stage(sbase, 1, A, lda, B, ldb, 16, tid);

    float acc[2][8][4] = {};

    for (int kt = 0; kt < nt; kt++) {
        if (kt + 2 < nt) {
            issue_stage(sbase, (kt + 2) % 3, A, lda, B, ldb, (kt + 2) * 16, tid);
            asm volatile("cp.async.wait_group %0;" :: "n"(2) : "memory");
        } else if (kt + 1 < nt) {
            asm volatile("cp.async.wait_group %0;" :: "n"(1) : "memory");
        } else {
            asm volatile("cp.async.wait_group %0;" :: "n"(0) : "memory");
        }
        __syncthreads();

        const float* AsF = smf + (kt % 3) * STAGE_F;
        const float* BsF = AsF + A_STAGE;

        #pragma unroll
        for (int h = 0; h < 2; h++) {
            const int k0 = h * 8;
            uint32_t afr[2][4], bfr[8][2];
            #pragma unroll
            for (int tm = 0; tm < 2; tm++) {
                const int mb = mw + tm * 16;
                afr[tm][0] = f2tf(AsF[(mb + g)     * ASTRF + k0 + t]);
                afr[tm][1] = f2tf(AsF[(mb + g + 8) * ASTRF + k0 + t]);
                afr[tm][2] = f2tf(AsF[(mb + g)     * ASTRF + k0 + t + 4]);
                afr[tm][3] = f2tf(AsF[(mb + g + 8) * ASTRF + k0 + t + 4]);
            }
            #pragma unroll
            for (int tn = 0; tn < 8; tn++) {
                const int nb = nw + tn * 8 + g;
                bfr[tn][0] = f2tf(BsF[(k0 + t)     * BSTRF + nb]);
                bfr[tn][1] = f2tf(BsF[(k0 + t + 4) * BSTRF + nb]);
            }
            #pragma unroll
            for (int tm = 0; tm < 2; tm++)
                #pragma unroll
                for (int tn = 0; tn < 8; tn++)
                    mma8(acc[tm][tn], afr[tm], bfr[tn]);
        }
        __syncthreads();
    }

    #pragma unroll
    for (int tm = 0; tm < 2; tm++) {
        #pragma unroll
        for (int tn = 0; tn < 8; tn++) {
            const int r0 = mw + tm * 16 + g;
            const int cc = nw + tn * 8 + 2 * t;
            *(float2*)&C[r0 * ldc + cc]       = make_float2(acc[tm][tn][0], acc[tm][tn][1]);
            *(float2*)&C[(r0 + 8) * ldc + cc] = make_float2(acc[tm][tn][2], acc[tm][tn][3]);
            if (C2) {
                *(float2*)&C2[r0 * ldc + cc] = make_float2(
                    __uint_as_float(f2tf(acc[tm][tn][0])), __uint_as_float(f2tf(acc[tm][tn][1])));
                *(float2*)&C2[(r0 + 8) * ldc + cc] = make_float2(
                    __uint_as_float(f2tf(acc[tm][tn][2])), __uint_as_float(f2tf(acc[tm][tn][3])));
            }
        }
    }
}

// Fused projections: qg (y 0..31), K (y 32..35), V (y 36..39). grid (16, 40).
__global__ __launch_bounds__(256, 2) void proj_fused_kernel(
    const float* __restrict__ x0, const float* __restrict__ x1,
    const float* __restrict__ qgw0, const float* __restrict__ qgw1,
    const float* __restrict__ kw0, const float* __restrict__ kw1,
    const float* __restrict__ vw0, const float* __restrict__ vw1,
    float* __restrict__ qg, float* __restrict__ kraw,
    float* __restrict__ vcache, float* __restrict__ vtf)
{
    const int tile = blockIdx.x;
    const int y = blockIdx.y;
    const float* A = (tile < 4) ? (x0 + (long)tile * 128 * WIDTH)
                                : (x1 + (long)(tile - 4) * 128 * WIDTH);
    const float* B;
    float* C;
    float* C2 = nullptr;
    int ldb, ldc;
    if (y < 32) {
        const int n = y >> 1, bn = (y & 1) * 128;
        B = ((tile < 4) ? qgw0 : qgw1) + (long)n * WIDTH * 256 + bn;
        ldb = 256;
        C = qg + (long)tile * 128 * (NH * 256) + n * 256 + bn;
        ldc = NH * 256;
    } else if (y < 36) {
        const int kk = y - 32;
        B = ((tile < 4) ? kw0 : kw1) + (long)kk * WIDTH * HD;
        ldb = HD;
        C = kraw + (long)tile * 128 * (KH * HD) + kk * HD;
        ldc = KH * HD;
    } else {
        const int kk = y - 36;
        B = ((tile < 4) ? vw0 : vw1) + (long)kk * WIDTH * HD;
        ldb = HD;
        C = vcache + (long)tile * 128 * (KH * HD) + kk * HD;
        C2 = vtf + (long)tile * 128 * (KH * HD) + kk * HD;
        ldc = KH * HD;
    }
    gemm_async_core(A, WIDTH, B, ldb, C, C2, ldc, WIDTH);
}

// output projection: grid (16, 16)
__global__ __launch_bounds__(256, 2) void proj_out_kernel(
    const float* __restrict__ enc,
    const float* __restrict__ ow0, const float* __restrict__ ow1,
    float* __restrict__ out)
{
    const int tile = blockIdx.x;
    const int bn = blockIdx.y * 128;
    const float* A = enc + (long)tile * 128 * (NH * HD);
    const float* B = ((tile < 4) ? ow0 : ow1) + bn;
    float* C = out + (long)tile * 128 * WIDTH + bn;
    gemm_async_core(A, NH * HD, B, WIDTH, C, nullptr, WIDTH, NH * HD);
}

// ---------------------------------------------------------------------------
// RMSNorm + RoPE
// ---------------------------------------------------------------------------
__global__ __launch_bounds__(128) void qnorm_rope(
    const float* __restrict__ qg, float* __restrict__ qout,
    const int* __restrict__ positions,
    const float* __restrict__ qn0, const float* __restrict__ qn1)
{
    int row  = blockIdx.x * 4 + (threadIdx.x >> 5);
    int lane = threadIdx.x & 31;
    int t = row >> 4;
    int n = row & 15;
    const float* src = qg + t * (NH * 256) + n * 256;

    float v0 = src[lane];
    float v1 = src[lane + 32];
    float v2 = src[lane + 64];
    float v3 = src[lane + 96];
    float ss = v0 * v0 + v1 * v1 + v2 * v2 + v3 * v3;
    #pragma unroll
    for (int o = 16; o; o >>= 1) ss += __shfl_xor_sync(0xffffffffu, ss, o);
    float inv = rsqrtf(ss * (1.0f / 128.0f) + 1e-6f);

    const float* qn = (t < T0) ? qn0 : qn1;
    v0 = v0 * inv * (1.0f + qn[lane]);
    v1 = v1 * inv * (1.0f + qn[lane + 32]);
    v2 = v2 * inv * (1.0f + qn[lane + 64]);
    v3 = v3 * inv * (1.0f + qn[lane + 96]);

    float p = (float)positions[t];
    float freq = powf(1000000.0f, -(float)lane / 32.0f);
    float s, c;
    sincosf(p * freq, &s, &c);

    const float SCL = 0.08838834764831845f;
    float* dst = qout + t * (NH * HD) + n * HD;
    dst[lane]      = __uint_as_float(f2tf((v0 * c - v1 * s) * SCL));
    dst[lane + 32] = __uint_as_float(f2tf((v1 * c + v0 * s) * SCL));
    dst[lane + 64] = __uint_as_float(f2tf(v2 * SCL));
    dst[lane + 96] = __uint_as_float(f2tf(v3 * SCL));
}

__global__ __launch_bounds__(128) void knorm_rope(
    const float* __restrict__ kraw, float* __restrict__ kcache,
    float* __restrict__ ktf,
    const int* __restrict__ positions,
    const float* __restrict__ kn0, const float* __restrict__ kn1)
{
    int row  = blockIdx.x * 4 + (threadIdx.x >> 5);
    int lane = threadIdx.x & 31;
    int t  = row >> 2;
    int kk = row & 3;
    const float* src = kraw + t * (KH * HD) + kk * HD;

    float v0 = src[lane];
    float v1 = src[lane + 32];
    float v2 = src[lane + 64];
    float v3 = src[lane + 96];
    float ss = v0 * v0 + v1 * v1 + v2 * v2 + v3 * v3;
    #pragma unroll
    for (int o = 16; o; o >>= 1) ss += __shfl_xor_sync(0xffffffffu, ss, o);
    float inv = rsqrtf(ss * (1.0f / 128.0f) + 1e-6f);

    const float* kn = (t < T0) ? kn0 : kn1;
    v0 = v0 * inv * (1.0f + kn[lane]);
    v1 = v1 * inv * (1.0f + kn[lane + 32]);
    v2 = v2 * inv * (1.0f + kn[lane + 64]);
    v3 = v3 * inv * (1.0f + kn[lane + 96]);

    float p = (float)positions[t];
    float freq = powf(1000000.0f, -(float)lane / 32.0f);
    float s, c;
    sincosf(p * freq, &s, &c);

    float r0 = v0 * c - v1 * s;
    float r1 = v1 * c + v0 * s;

    float* dst = kcache + t * (KH * HD) + kk * HD;
    dst[lane]      = r0;
    dst[lane + 32] = r1;
    dst[lane + 64] = v2;
    dst[lane + 96] = v3;

    float* dtf = ktf + t * (KH * HD) + kk * HD;
    dtf[lane]      = __uint_as_float(f2tf(r0));
    dtf[lane + 32] = __uint_as_float(f2tf(r1));
    dtf[lane + 64] = __uint_as_float(f2tf(v2));
    dtf[lane + 96] = __uint_as_float(f2tf(v3));
}

// ---------------------------------------------------------------------------
// Flash attention: 2 GQA heads x 64 queries per CTA, 256 threads (R7 config).
// Inputs pre-rounded to tf32 -> fragment loads are plain reinterprets.
// Hybrid MUFU/poly exp in softmax. SSTR=65 (softmax conflicts 8-way -> 2-way).
// smem (floats): Q tf32 [128][132] | 3 x KV [64][132] | S [128][65]
// ---------------------------------------------------------------------------
#define QSTR 132
#define KVSTR 132
#define SSTR 65
#define SLOT_F (64 * KVSTR)
#define AQ_OFF 0
#define AKV_OFF (128 * QSTR)
#define AS_OFF (AKV_OFF + 3 * SLOT_F)
#define ATT_SMEM_F (AS_OFF + 128 * SSTR)

__device__ __forceinline__ void att_issue(
    uint32_t kvbase, int slot, const float* __restrict__ src, int sb, int tid)
{
    const uint32_t dst = kvbase + slot * (SLOT_F * 4);
    #pragma unroll
    for (int i = 0; i < 8; i++) {
        const int lin = tid + 256 * i;
        const int r = lin >> 5;
        const int c4 = (lin & 31) * 4;
        cpasync16(dst + (r * KVSTR + c4) * 4, src + (long)(sb + r) * (KH * HD) + c4);
    }
    asm volatile("cp.async.commit_group;" ::: "memory");
}

__global__ __launch_bounds__(256, 1) void attn_kernel(
    const float* __restrict__ q, const float* __restrict__ ktf,
    const float* __restrict__ vtf, const float* __restrict__ qg,
    float* __restrict__ enc)
{
    extern __shared__ float smf[];
    const uint32_t* Qs = (const uint32_t*)(smf + AQ_OFF);
    uint32_t* Qw = (uint32_t*)(smf + AQ_OFF);
    float*    Ss = smf + AS_OFF;
    const uint32_t kvbase = smem_u32(smf + AKV_OFF);
    __shared__ float m_s[128], l_s[128], a_s[128];

    const int tid = threadIdx.x;
    const int lane = tid & 31;
    const int g = lane >> 2;
    const int t = lane & 3;
    const int wid = tid >> 5;
    const int wm = (wid >> 1) * 32;  // warp M base (2 m16 tiles)
    const int wn = wid & 1;
    const int qt = gridDim.x - 1 - blockIdx.x;   // heavy tiles first
    const int n0 = blockIdx.y * 2;               // head pair (same kvh)
    const int kvh = n0 >> 2;
    const int qbase = qt * 64;

    const float* kbase = ktf + kvh * HD;
    const float* vbase = vtf + kvh * HD;

    // preamble: kick off K(0), V(0); stage Q (already tf32)
    att_issue(kvbase, 0, kbase, 0, tid);
    att_issue(kvbase, 1, vbase, 0, tid);
    for (int idx = tid; idx < 128 * 128; idx += 256) {
        int r = idx >> 7, c = idx & 127;
        int head = n0 + (r >> 6);
        int qrow = qbase + (r & 63);
        Qw[r * QSTR + c] = __float_as_uint(q[qrow * (NH * HD) + head * HD + c]);
    }
    if (tid < 128) { m_s[tid] = -3.0e38f; l_s[tid] = 0.0f; }

    float accO[2][8][4] = {};

    for (int j = 0; j <= qt; j++) {
        const int nsb = (j + 1 <= qt) ? (j + 1) * 64 : qt * 64;

        asm volatile("cp.async.wait_group %0;" :: "n"(1) : "memory");
        __syncthreads();

        att_issue(kvbase, (2 * j + 2) % 3, kbase, nsb, tid);

        // ---- S = Q K^T (128x64) from slot (2j)%3. Warp tile 32x32. ----
        const uint32_t* Kf = (const uint32_t*)(smf + AKV_OFF + ((2 * j) % 3) * SLOT_F);
        float sacc[2][4][4] = {};
        #pragma unroll
        for (int ks = 0; ks < 16; ks++) {
            const int k0 = ks * 8;
            uint32_t afr[2][4], bfr[4][2];
            #pragma unroll
            for (int tm = 0; tm < 2; tm++) {
                const int mb = wm + tm * 16;
                afr[tm][0] = Qs[(mb + g)     * QSTR + k0 + t];
                afr[tm][1] = Qs[(mb + g + 8) * QSTR + k0 + t];
                afr[tm][2] = Qs[(mb + g)     * QSTR + k0 + t + 4];
                afr[tm][3] = Qs[(mb + g + 8) * QSTR + k0 + t + 4];
            }
            #pragma unroll
            for (int tn = 0; tn < 4; tn++) {
                const int key = wn * 32 + tn * 8 + g;
                bfr[tn][0] = Kf[key * KVSTR + k0 + t];
                bfr[tn][1] = Kf[key * KVSTR + k0 + t + 4];
            }
            #pragma unroll
            for (int tm = 0; tm < 2; tm++)
                #pragma unroll
                for (int tn = 0; tn < 4; tn++)
                    mma8(sacc[tm][tn], afr[tm], bfr[tn]);
        }
        const bool diag = (j == qt);
        #pragma unroll
        for (int tm = 0; tm < 2; tm++) {
            #pragma unroll
            for (int tn = 0; tn < 4; tn++) {
                const int cc = wn * 32 + tn * 8 + 2 * t;
                const int r0 = wm + tm * 16 + g, r1 = r0 + 8;
                const int q0 = r0 & 63, q1 = r1 & 63;
                float v0 = sacc[tm][tn][0], v1 = sacc[tm][tn][1];
                float v2 = sacc[tm][tn][2], v3 = sacc[tm][tn][3];
                if (diag) {
                    if (cc     > q0) v0 = NEGV;
                    if (cc + 1 > q0) v1 = NEGV;
                    if (cc     > q1) v2 = NEGV;
                    if (cc + 1 > q1) v3 = NEGV;
                }
                Ss[r0 * SSTR + cc] = v0; Ss[r0 * SSTR + cc + 1] = v1;
                Ss[r1 * SSTR + cc] = v2; Ss[r1 * SSTR + cc + 1] = v3;
            }
        }
        __syncthreads();

        att_issue(kvbase, (2 * j) % 3, vbase, nsb, tid);

        asm volatile("cp.async.wait_group %0;" :: "n"(2) : "memory");
        __syncthreads();

        // ---- online softmax: 2 threads/row, 32 cols; hybrid MUFU/poly exp ----
        {
            int r = tid >> 1;
            int qq = tid & 1;
            float* row = Ss + r * SSTR + qq * 32;
            float mold = m_s[r];
            float rmax = -3.0e38f;
            #pragma unroll
            for (int c = 0; c < 32; c++) rmax = fmaxf(rmax, row[c]);
            rmax = fmaxf(rmax, __shfl_xor_sync(0xffffffffu, rmax, 1));
            float mn = fmaxf(mold, rmax);
            float sum = 0.0f;
            #pragma unroll
            for (int c = 0; c < 32; c++) {
                float x = row[c] - mn;
                float pv = ((c & 7) < 5) ? __expf(x) : exp_poly(x);
                sum += pv;
                row[c] = __uint_as_float(f2tf(pv));
            }
            sum += __shfl_xor_sync(0xffffffffu, sum, 1);
            if (qq == 0) {
                float al = __expf(mold - mn);
                l_s[r] = l_s[r] * al + sum;
                m_s[r] = mn;
                a_s[r] = al;
            }
        }
        __syncthreads();

        // ---- rescale + O += P V from slot (2j+1)%3. Warp tile 32x64. ----
        const uint32_t* Vf = (const uint32_t*)(smf + AKV_OFF + ((2 * j + 1) % 3) * SLOT_F);
        #pragma unroll
        for (int tm = 0; tm < 2; tm++) {
            const float al0 = a_s[wm + tm * 16 + g];
            const float al1 = a_s[wm + tm * 16 + g + 8];
            #pragma unroll
            for (int tn = 0; tn < 8; tn++) {
                accO[tm][tn][0] *= al0; accO[tm][tn][1] *= al0;
                accO[tm][tn][2] *= al1; accO[tm][tn][3] *= al1;
            }
        }
        const uint32_t* Ps = (const uint32_t*)Ss;
        #pragma unroll
        for (int ks = 0; ks < 8; ks++) {
            const int k0 = ks * 8;
            uint32_t afr[2][4], bfr[8][2];
            #pragma unroll
            for (int tm = 0; tm < 2; tm++) {
                const int mb = wm + tm * 16;
                afr[tm][0] = Ps[(mb + g)     * SSTR + k0 + t];
                afr[tm][1] = Ps[(mb + g + 8) * SSTR + k0 + t];
                afr[tm][2] = Ps[(mb + g)     * SSTR + k0 + t + 4];
                afr[tm][3] = Ps[(mb + g + 8) * SSTR + k0 + t + 4];
            }
            #pragma unroll
            for (int tn = 0; tn < 8; tn++) {
                const int hb = wn * 64 + tn * 8 + g;
                bfr[tn][0] = Vf[(k0 + t)     * KVSTR + hb];
                bfr[tn][1] = Vf[(k0 + t + 4) * KVSTR + hb];
            }
            #pragma unroll
            for (int tm = 0; tm < 2; tm++)
                #pragma unroll
                for (int tn = 0; tn < 8; tn++)
                    mma8(accO[tm][tn], afr[tm], bfr[tn]);
        }
    }

    asm volatile("cp.async.wait_group %0;" :: "n"(0) : "memory");

    // epilogue: 1/l scaling + fused sigmoid gate (hybrid exp)
    #pragma unroll
    for (int tm = 0; tm < 2; tm++) {
        const int r0 = wm + tm * 16 + g;
        const int r1 = r0 + 8;
        const int h0 = n0 + (r0 >> 6), h1 = n0 + (r1 >> 6);
        const int qr0 = qbase + (r0 & 63), qr1 = qbase + (r1 & 63);
        const float inv0 = 1.0f / l_s[r0];
        const float inv1 = 1.0f / l_s[r1];
        #pragma unroll
        for (int tn = 0; tn < 8; tn++) {
            const int cc = wn * 64 + tn * 8 + 2 * t;
            float2 gg0 = *(const float2*)&qg[qr0 * (NH * 256) + h0 * 256 + 128 + cc];
            float2 gg1 = *(const float2*)&qg[qr1 * (NH * 256) + h1 * 256 + 128 + cc];
            float e00, e01, e10, e11;
            if (tn & 1) {
                e00 = exp_poly(-gg0.x); e01 = exp_poly(-gg0.y);
                e10 = exp_poly(-gg1.x); e11 = exp_poly(-gg1.y);
            } else {
                e00 = __expf(-gg0.x); e01 = __expf(-gg0.y);
                e10 = __expf(-gg1.x); e11 = __expf(-gg1.y);
            }
            float s00 = 1.0f / (1.0f + e00);
            float s01 = 1.0f / (1.0f + e01);
            float s10 = 1.0f / (1.0f + e10);
            float s11 = 1.0f / (1.0f + e11);
            float* d0 = enc + qr0 * (NH * HD) + h0 * HD + cc;
            float* d1 = enc + qr1 * (NH * HD) + h1 * HD + cc;
            *(float2*)d0 = make_float2(accO[tm][tn][0] * inv0 * s00, accO[tm][tn][1] * inv0 * s01);
            *(float2*)d1 = make_float2(accO[tm][tn][2] * inv1 * s10, accO[tm][tn][3] * inv1 * s11);
        }
    }
}

// ---------------------------------------------------------------------------
extern "C" void kernel_launch(void* const* d_in, const int* in_sizes, int n_in,
                              void* d_out, int out_size)
{
    const float* x0    = (const float*)d_in[0];
    const float* x1    = (const float*)d_in[1];
    const int*   pos   = (const int*)d_in[2];
    const float* qg_w0 = (const float*)d_in[4];
    const float* k_w0  = (const float*)d_in[5];
    const float* v_w0  = (const float*)d_in[6];
    const float* qn0   = (const float*)d_in[7];
    const float* kn0   = (const float*)d_in[8];
    const float* o_w0  = (const float*)d_in[9];
    const float* qg_w1 = (const float*)d_in[10];
    const float* k_w1  = (const float*)d_in[11];
    const float* v_w1  = (const float*)d_in[12];
    const float* qn1   = (const float*)d_in[13];
    const float* kn1   = (const float*)d_in[14];
    const float* o_w1  = (const float*)d_in[15];

    float* out = (float*)d_out;

    float *qg, *kraw, *q, *enc, *ktf, *vtf;
    cudaGetSymbolAddress((void**)&qg,   g_qg);
    cudaGetSymbolAddress((void**)&kraw, g_kraw);
    cudaGetSymbolAddress((void**)&q,    g_q);
    cudaGetSymbolAddress((void**)&enc,  g_enc);
    cudaGetSymbolAddress((void**)&ktf,  g_ktf);
    cudaGetSymbolAddress((void**)&vtf,  g_vtf);

    cudaFuncSetAttribute(proj_fused_kernel, cudaFuncAttributeMaxDynamicSharedMemorySize, GEMM_SMEM_BYTES);
    cudaFuncSetAttribute(proj_out_kernel,   cudaFuncAttributeMaxDynamicSharedMemorySize, GEMM_SMEM_BYTES);
    cudaFuncSetAttribute(attn_kernel, cudaFuncAttributeMaxDynamicSharedMemorySize,
                         ATT_SMEM_F * sizeof(float));

    // all projections in one launch (V dual-written: exact -> d_out, tf32 -> scratch)
    proj_fused_kernel<<<dim3(16, 40), 256, GEMM_SMEM_BYTES>>>(
        x0, x1, qg_w0, qg_w1, k_w0, k_w1, v_w0, v_w1, qg, kraw, out + VC_BASE, vtf);

    // norms + rope (K dual-written; Q pre-rounded to tf32)
    qnorm_rope<<<TT*NH/4, 128>>>(qg, q, pos, qn0, qn1);
    knorm_rope<<<TT*KH/4, 128>>>(kraw, out + KC_BASE, ktf, pos, kn0, kn1);

    // attention: 2 GQA heads per CTA, pre-rounded inputs, hybrid exp, fused gate
    attn_kernel<<<dim3(TT/64, NH/2), 256, ATT_SMEM_F * sizeof(float)>>>(
        q, ktf, vtf, qg, enc);

    // output projection
    proj_out_kernel<<<dim3(16, 16), 256, GEMM_SMEM_BYTES>>>(enc, o_w0, o_w1, out);
}

// round 10
// speedup vs baseline: 1.0445x; 1.0439x over previous
#include <cuda_runtime.h>
#include <cuda_bf16.h>
#include <math.h>
#include <stdint.h>

// Problem constants
#define T0 512
#define TT 2048
#define WIDTH 2048
#define NH 16
#define KH 4
#define HD 128
#define KC_BASE (TT*WIDTH)
#define VC_BASE (KC_BASE + TT*KH*HD)
#define NEGV -2.3819763e38f

// Scratch
__device__ float g_qg[TT * NH * 256];
__device__ float g_kraw[TT * KH * HD];
__device__ float g_q[TT * NH * HD];     // tf32-rounded q
__device__ float g_ktf[TT * KH * HD];   // tf32-rounded roped K
__device__ float g_vtf[TT * KH * HD];   // tf32-rounded V
__device__ float g_enc[TT * NH * HD];

// ---------------------------------------------------------------------------
// helpers
// ---------------------------------------------------------------------------
__device__ __forceinline__ uint32_t f2tf(float f) {
    uint32_t r;
    asm("cvt.rna.tf32.f32 %0, %1;" : "=r"(r) : "f"(f));
    return r;
}

__device__ __forceinline__ uint32_t smem_u32(const void* p) {
    uint32_t a;
    asm("{ .reg .u64 t; cvta.to.shared.u64 t, %1; cvt.u32.u64 %0, t; }"
        : "=r"(a) : "l"(p));
    return a;
}

__device__ __forceinline__ void cpasync16(uint32_t s, const float* g) {
    asm volatile("cp.async.ca.shared.global [%0], [%1], 16;" :: "r"(s), "l"(g));
}

// m16n8k8 tf32 MMA, fp32 accumulate.
__device__ __forceinline__ void mma8(float* c, const uint32_t* a, const uint32_t* b) {
    asm volatile(
        "mma.sync.aligned.m16n8k8.row.col.f32.tf32.tf32.f32 "
        "{%0,%1,%2,%3},{%4,%5,%6,%7},{%8,%9},{%0,%1,%2,%3};"
        : "+f"(c[0]), "+f"(c[1]), "+f"(c[2]), "+f"(c[3])
        : "r"(a[0]), "r"(a[1]), "r"(a[2]), "r"(a[3]), "r"(b[0]), "r"(b[1]));
}

// FMA-pipe exp (exp2 poly, |rel err| ~4e-5 << tf32 quantization).
__device__ __forceinline__ float exp_poly(float x) {
    float xl = x * 1.4426950408889634f;
    xl = fmaxf(fminf(xl, 125.0f), -125.0f);
    float nf = rintf(xl);
    float fr = xl - nf;
    float t = fmaf(0.0096183425f, fr, 0.055503327f);
    t = fmaf(t, fr, 0.24022651f);
    t = fmaf(t, fr, 0.69314718f);
    t = fmaf(t, fr, 1.0f);
    return __uint_as_float(__float_as_uint(t) + (int)nf * 8388608);
}

// ---------------------------------------------------------------------------
// cp.async pipelined tf32 GEMM core. Optional second (tf32-rounded) output.
// ---------------------------------------------------------------------------
#define ASTRF 20
#define BSTRF 136
#define A_STAGE (128 * ASTRF)
#define B_STAGE (16 * BSTRF)
#define STAGE_F (A_STAGE + B_STAGE)
#define GEMM_SMEM_BYTES (3 * STAGE_F * 4)

__device__ __forceinline__ void issue_stage(
    uint32_t sbase, int stage, const float* A, int lda,
    const float* B, int ldb, int k0, int tid)
{
    const uint32_t aS = sbase + stage * (STAGE_F * 4);
    const uint32_t bS = aS + A_STAGE * 4;
    const int ar = tid >> 2, ak = (tid & 3) * 4;
    const int br = tid >> 5, bc = (tid & 31) * 4;
    cpasync16(aS + (ar * ASTRF + ak) * 4,          A + (long)ar * lda + k0 + ak);
    cpasync16(aS + ((64 + ar) * ASTRF + ak) * 4,   A + (long)(64 + ar) * lda + k0 + ak);
    cpasync16(bS + (br * BSTRF + bc) * 4,          B + (long)(k0 + br) * ldb + bc);
    cpasync16(bS + ((8 + br) * BSTRF + bc) * 4,    B + (long)(k0 + 8 + br) * ldb + bc);
    asm volatile("cp.async.commit_group;" ::: "memory");
}

__device__ void gemm_async_core(
    const float* __restrict__ A, int lda,
    const float* __restrict__ B, int ldb,
    float* __restrict__ C, float* __restrict__ C2, int ldc, int Kdim)
{
    extern __shared__ float smf[];
    const uint32_t sbase = smem_u32(smf);

    const int tid = threadIdx.x;
    const int lane = tid & 31;
    const int g = lane >> 2;
    const int t = lane & 3;
    const int wid = tid >> 5;
    const int mw = (wid >> 1) * 32;
    const int nw = (wid & 1) * 64;

    const int nt = Kdim / 16;

    issue_stage(sbase, 0, A, lda, B, ldb, 0, tid);
    issue_stage(sbase, 1, A, lda, B, ldb, 16, tid);

    float acc[2][8][4] = {};

    for (int kt = 0; kt < nt; kt++) {
        if (kt + 2 < nt) {
            issue_stage(sbase, (kt + 2) % 3, A, lda, B, ldb, (kt + 2) * 16, tid);
            asm volatile("cp.async.wait_group %0;" :: "n"(2) : "memory");
        } else if (kt + 1 < nt) {
            asm volatile("cp.async.wait_group %0;" :: "n"(1) : "memory");
        } else {
            asm volatile("cp.async.wait_group %0;" :: "n"(0) : "memory");
        }
        __syncthreads();

        const float* AsF = smf + (kt % 3) * STAGE_F;
        const float* BsF = AsF + A_STAGE;

        #pragma unroll
        for (int h = 0; h < 2; h++) {
            const int k0 = h * 8;
            uint32_t afr[2][4], bfr[8][2];
            #pragma unroll
            for (int tm = 0; tm < 2; tm++) {
                const int mb = mw + tm * 16;
                afr[tm][0] = f2tf(AsF[(mb + g)     * ASTRF + k0 + t]);
                afr[tm][1] = f2tf(AsF[(mb + g + 8) * ASTRF + k0 + t]);
                afr[tm][2] = f2tf(AsF[(mb + g)     * ASTRF + k0 + t + 4]);
                afr[tm][3] = f2tf(AsF[(mb + g + 8) * ASTRF + k0 + t + 4]);
            }
            #pragma unroll
            for (int tn = 0; tn < 8; tn++) {
                const int nb = nw + tn * 8 + g;
                bfr[tn][0] = f2tf(BsF[(k0 + t)     * BSTRF + nb]);
                bfr[tn][1] = f2tf(BsF[(k0 + t + 4) * BSTRF + nb]);
            }
            #pragma unroll
            for (int tm = 0; tm < 2; tm++)
                #pragma unroll
                for (int tn = 0; tn < 8; tn++)
                    mma8(acc[tm][tn], afr[tm], bfr[tn]);
        }
        __syncthreads();
    }

    #pragma unroll
    for (int tm = 0; tm < 2; tm++) {
        #pragma unroll
        for (int tn = 0; tn < 8; tn++) {
            const int r0 = mw + tm * 16 + g;
            const int cc = nw + tn * 8 + 2 * t;
            *(float2*)&C[r0 * ldc + cc]       = make_float2(acc[tm][tn][0], acc[tm][tn][1]);
            *(float2*)&C[(r0 + 8) * ldc + cc] = make_float2(acc[tm][tn][2], acc[tm][tn][3]);
            if (C2) {
                *(float2*)&C2[r0 * ldc + cc] = make_float2(
                    __uint_as_float(f2tf(acc[tm][tn][0])), __uint_as_float(f2tf(acc[tm][tn][1])));
                *(float2*)&C2[(r0 + 8) * ldc + cc] = make_float2(
                    __uint_as_float(f2tf(acc[tm][tn][2])), __uint_as_float(f2tf(acc[tm][tn][3])));
            }
        }
    }
}

// Fused projections: qg (y 0..31), K (y 32..35), V (y 36..39). grid (16, 40).
__global__ __launch_bounds__(256, 2) void proj_fused_kernel(
    const float* __restrict__ x0, const float* __restrict__ x1,
    const float* __restrict__ qgw0, const float* __restrict__ qgw1,
    const float* __restrict__ kw0, const float* __restrict__ kw1,
    const float* __restrict__ vw0, const float* __restrict__ vw1,
    float* __restrict__ qg, float* __restrict__ kraw,
    float* __restrict__ vcache, float* __restrict__ vtf)
{
    const int tile = blockIdx.x;
    const int y = blockIdx.y;
    const float* A = (tile < 4) ? (x0 + (long)tile * 128 * WIDTH)
                                : (x1 + (long)(tile - 4) * 128 * WIDTH);
    const float* B;
    float* C;
    float* C2 = nullptr;
    int ldb, ldc;
    if (y < 32) {
        const int n = y >> 1, bn = (y & 1) * 128;
        B = ((tile < 4) ? qgw0 : qgw1) + (long)n * WIDTH * 256 + bn;
        ldb = 256;
        C = qg + (long)tile * 128 * (NH * 256) + n * 256 + bn;
        ldc = NH * 256;
    } else if (y < 36) {
        const int kk = y - 32;
        B = ((tile < 4) ? kw0 : kw1) + (long)kk * WIDTH * HD;
        ldb = HD;
        C = kraw + (long)tile * 128 * (KH * HD) + kk * HD;
        ldc = KH * HD;
    } else {
        const int kk = y - 36;
        B = ((tile < 4) ? vw0 : vw1) + (long)kk * WIDTH * HD;
        ldb = HD;
        C = vcache + (long)tile * 128 * (KH * HD) + kk * HD;
        C2 = vtf + (long)tile * 128 * (KH * HD) + kk * HD;
        ldc = KH * HD;
    }
    gemm_async_core(A, WIDTH, B, ldb, C, C2, ldc, WIDTH);
}

// output projection: grid (16, 16)
__global__ __launch_bounds__(256, 2) void proj_out_kernel(
    const float* __restrict__ enc,
    const float* __restrict__ ow0, const float* __restrict__ ow1,
    float* __restrict__ out)
{
    const int tile = blockIdx.x;
    const int bn = blockIdx.y * 128;
    const float* A = enc + (long)tile * 128 * (NH * HD);
    const float* B = ((tile < 4) ? ow0 : ow1) + bn;
    float* C = out + (long)tile * 128 * WIDTH + bn;
    gemm_async_core(A, NH * HD, B, WIDTH, C, nullptr, WIDTH, NH * HD);
}

// ---------------------------------------------------------------------------
// RMSNorm + RoPE
// ---------------------------------------------------------------------------
__global__ __launch_bounds__(128) void qnorm_rope(
    const float* __restrict__ qg, float* __restrict__ qout,
    const int* __restrict__ positions,
    const float* __restrict__ qn0, const float* __restrict__ qn1)
{
    int row  = blockIdx.x * 4 + (threadIdx.x >> 5);
    int lane = threadIdx.x & 31;
    int t = row >> 4;
    int n = row & 15;
    const float* src = qg + t * (NH * 256) + n * 256;

    float v0 = src[lane];
    float v1 = src[lane + 32];
    float v2 = src[lane + 64];
    float v3 = src[lane + 96];
    float ss = v0 * v0 + v1 * v1 + v2 * v2 + v3 * v3;
    #pragma unroll
    for (int o = 16; o; o >>= 1) ss += __shfl_xor_sync(0xffffffffu, ss, o);
    float inv = rsqrtf(ss * (1.0f / 128.0f) + 1e-6f);

    const float* qn = (t < T0) ? qn0 : qn1;
    v0 = v0 * inv * (1.0f + qn[lane]);
    v1 = v1 * inv * (1.0f + qn[lane + 32]);
    v2 = v2 * inv * (1.0f + qn[lane + 64]);
    v3 = v3 * inv * (1.0f + qn[lane + 96]);

    float p = (float)positions[t];
    float freq = powf(1000000.0f, -(float)lane / 32.0f);
    float s, c;
    sincosf(p * freq, &s, &c);

    const float SCL = 0.08838834764831845f;
    float* dst = qout + t * (NH * HD) + n * HD;
    dst[lane]      = __uint_as_float(f2tf((v0 * c - v1 * s) * SCL));
    dst[lane + 32] = __uint_as_float(f2tf((v1 * c + v0 * s) * SCL));
    dst[lane + 64] = __uint_as_float(f2tf(v2 * SCL));
    dst[lane + 96] = __uint_as_float(f2tf(v3 * SCL));
}

__global__ __launch_bounds__(128) void knorm_rope(
    const float* __restrict__ kraw, float* __restrict__ kcache,
    float* __restrict__ ktf,
    const int* __restrict__ positions,
    const float* __restrict__ kn0, const float* __restrict__ kn1)
{
    int row  = blockIdx.x * 4 + (threadIdx.x >> 5);
    int lane = threadIdx.x & 31;
    int t  = row >> 2;
    int kk = row & 3;
    const float* src = kraw + t * (KH * HD) + kk * HD;

    float v0 = src[lane];
    float v1 = src[lane + 32];
    float v2 = src[lane + 64];
    float v3 = src[lane + 96];
    float ss = v0 * v0 + v1 * v1 + v2 * v2 + v3 * v3;
    #pragma unroll
    for (int o = 16; o; o >>= 1) ss += __shfl_xor_sync(0xffffffffu, ss, o);
    float inv = rsqrtf(ss * (1.0f / 128.0f) + 1e-6f);

    const float* kn = (t < T0) ? kn0 : kn1;
    v0 = v0 * inv * (1.0f + kn[lane]);
    v1 = v1 * inv * (1.0f + kn[lane + 32]);
    v2 = v2 * inv * (1.0f + kn[lane + 64]);
    v3 = v3 * inv * (1.0f + kn[lane + 96]);

    float p = (float)positions[t];
    float freq = powf(1000000.0f, -(float)lane / 32.0f);
    float s, c;
    sincosf(p * freq, &s, &c);

    float r0 = v0 * c - v1 * s;
    float r1 = v1 * c + v0 * s;

    float* dst = kcache + t * (KH * HD) + kk * HD;
    dst[lane]      = r0;
    dst[lane + 32] = r1;
    dst[lane + 64] = v2;
    dst[lane + 96] = v3;

    float* dtf = ktf + t * (KH * HD) + kk * HD;
    dtf[lane]      = __uint_as_float(f2tf(r0));
    dtf[lane + 32] = __uint_as_float(f2tf(r1));
    dtf[lane + 64] = __uint_as_float(f2tf(v2));
    dtf[lane + 96] = __uint_as_float(f2tf(v3));
}

// ---------------------------------------------------------------------------
// Flash attention, FA2-style: warp owns 16 full rows (2 GQA heads x 64q per
// CTA, 8 warps). Register-resident online softmax (no smem S / m / l, no
// softmax barrier). P in warp-private smem (stride 68, conflict-free).
// 3 barriers/iter, 3-slot rotating cp.async K/V pipeline. 256 threads.
// smem (floats): Q tf32 [128][132] | 3 x KV [64][132] | P 8 x [16][68]
// ---------------------------------------------------------------------------
#define QSTR 132
#define KVSTR 132
#define PSTR 68
#define SLOT_F (64 * KVSTR)
#define AQ_OFF 0
#define AKV_OFF (128 * QSTR)
#define AP_OFF (AKV_OFF + 3 * SLOT_F)
#define ATT_SMEM_F (AP_OFF + 8 * 16 * PSTR)

__device__ __forceinline__ void att_issue(
    uint32_t kvbase, int slot, const float* __restrict__ src, int sb, int tid)
{
    const uint32_t dst = kvbase + slot * (SLOT_F * 4);
    #pragma unroll
    for (int i = 0; i < 8; i++) {
        const int lin = tid + 256 * i;
        const int r = lin >> 5;
        const int c4 = (lin & 31) * 4;
        cpasync16(dst + (r * KVSTR + c4) * 4, src + (long)(sb + r) * (KH * HD) + c4);
    }
    asm volatile("cp.async.commit_group;" ::: "memory");
}

__global__ __launch_bounds__(256, 1) void attn_kernel(
    const float* __restrict__ q, const float* __restrict__ ktf,
    const float* __restrict__ vtf, const float* __restrict__ qg,
    float* __restrict__ enc)
{
    extern __shared__ float smf[];
    const uint32_t* Qs = (const uint32_t*)(smf + AQ_OFF);
    uint32_t* Qw = (uint32_t*)(smf + AQ_OFF);
    const uint32_t kvbase = smem_u32(smf + AKV_OFF);

    const int tid = threadIdx.x;
    const int lane = tid & 31;
    const int g = lane >> 2;
    const int t = lane & 3;
    const int wid = tid >> 5;
    const int mW = wid * 16;                     // warp row base (0..112)
    const int qt = gridDim.x - 1 - blockIdx.x;   // heavy tiles first
    const int n0 = blockIdx.y * 2;               // head pair (same kvh)
    const int kvh = n0 >> 2;
    const int qbase = qt * 64;

    uint32_t* Pw = (uint32_t*)(smf + AP_OFF + wid * 16 * PSTR);

    const float* kbase = ktf + kvh * HD;
    const float* vbase = vtf + kvh * HD;

    // preamble: kick off K(0), V(0); stage Q (already tf32) as float4 copies
    att_issue(kvbase, 0, kbase, 0, tid);
    att_issue(kvbase, 1, vbase, 0, tid);
    for (int idx = tid; idx < 128 * 32; idx += 256) {
        int r = idx >> 5, c4 = (idx & 31) * 4;
        int head = n0 + (r >> 6);
        int qrow = qbase + (r & 63);
        float4 v = *(const float4*)&q[qrow * (NH * HD) + head * HD + c4];
        *(float4*)&Qw[r * QSTR + c4] = v;
    }

    // register softmax state: rows mW+g (0) and mW+g+8 (1)
    float m0 = -3.0e38f, m1 = -3.0e38f, l0 = 0.0f, l1 = 0.0f;
    float accO[16][4] = {};   // 16 n-tiles x 128 cols

    for (int j = 0; j <= qt; j++) {
        const int nsb = (j + 1 <= qt) ? (j + 1) * 64 : qt * 64;

        // K(j) ready (V(j) may still be in flight)
        asm volatile("cp.async.wait_group %0;" :: "n"(1) : "memory");
        __syncthreads();

        att_issue(kvbase, (2 * j + 2) % 3, kbase, nsb, tid);

        // ---- S = Q K^T: warp tile 16 rows x 64 keys, slot (2j)%3 ----
        const uint32_t* Kf = (const uint32_t*)(smf + AKV_OFF + ((2 * j) % 3) * SLOT_F);
        float sacc[8][4] = {};
        #pragma unroll
        for (int ks = 0; ks < 16; ks++) {
            const int k0 = ks * 8;
            uint32_t afr[4], bfr[8][2];
            afr[0] = Qs[(mW + g)     * QSTR + k0 + t];
            afr[1] = Qs[(mW + g + 8) * QSTR + k0 + t];
            afr[2] = Qs[(mW + g)     * QSTR + k0 + t + 4];
            afr[3] = Qs[(mW + g + 8) * QSTR + k0 + t + 4];
            #pragma unroll
            for (int tn = 0; tn < 8; tn++) {
                const int key = tn * 8 + g;
                bfr[tn][0] = Kf[key * KVSTR + k0 + t];
                bfr[tn][1] = Kf[key * KVSTR + k0 + t + 4];
            }
            #pragma unroll
            for (int tn = 0; tn < 8; tn++) mma8(sacc[tn], afr, bfr[tn]);
        }
        __syncthreads();   // all warps done reading K(j); slot free

        att_issue(kvbase, (2 * j) % 3, vbase, nsb, tid);

        // ---- causal mask + register online softmax ----
        const int q0 = (mW + g) & 63, q1 = (mW + g + 8) & 63;
        if (j == qt) {
            #pragma unroll
            for (int tn = 0; tn < 8; tn++) {
                const int cc = tn * 8 + 2 * t;
                if (cc     > q0) sacc[tn][0] = NEGV;
                if (cc + 1 > q0) sacc[tn][1] = NEGV;
                if (cc     > q1) sacc[tn][2] = NEGV;
                if (cc + 1 > q1) sacc[tn][3] = NEGV;
            }
        }
        float rmax0 = -3.0e38f, rmax1 = -3.0e38f;
        #pragma unroll
        for (int tn = 0; tn < 8; tn++) {
            rmax0 = fmaxf(rmax0, fmaxf(sacc[tn][0], sacc[tn][1]));
            rmax1 = fmaxf(rmax1, fmaxf(sacc[tn][2], sacc[tn][3]));
        }
        rmax0 = fmaxf(rmax0, __shfl_xor_sync(0xffffffffu, rmax0, 1));
        rmax0 = fmaxf(rmax0, __shfl_xor_sync(0xffffffffu, rmax0, 2));
        rmax1 = fmaxf(rmax1, __shfl_xor_sync(0xffffffffu, rmax1, 1));
        rmax1 = fmaxf(rmax1, __shfl_xor_sync(0xffffffffu, rmax1, 2));
        const float mn0 = fmaxf(m0, rmax0);
        const float mn1 = fmaxf(m1, rmax1);
        const float al0 = __expf(m0 - mn0);
        const float al1 = __expf(m1 - mn1);
        m0 = mn0; m1 = mn1;

        float sum0 = 0.0f, sum1 = 0.0f;
        #pragma unroll
        for (int tn = 0; tn < 8; tn++) {
            float p0, p1, p2, p3;
            if (tn & 1) {
                p0 = exp_poly(sacc[tn][0] - mn0); p1 = exp_poly(sacc[tn][1] - mn0);
                p2 = exp_poly(sacc[tn][2] - mn1); p3 = exp_poly(sacc[tn][3] - mn1);
            } else {
                p0 = __expf(sacc[tn][0] - mn0); p1 = __expf(sacc[tn][1] - mn0);
                p2 = __expf(sacc[tn][2] - mn1); p3 = __expf(sacc[tn][3] - mn1);
            }
            sum0 += p0 + p1;
            sum1 += p2 + p3;
            // write P tf32 into warp-private smem (no barrier needed)
            const int cc = tn * 8 + 2 * t;
            uint32_t u0 = f2tf(p0), u1 = f2tf(p1), u2 = f2tf(p2), u3 = f2tf(p3);
            Pw[g * PSTR + cc]           = u0;
            Pw[g * PSTR + cc + 1]       = u1;
            Pw[(g + 8) * PSTR + cc]     = u2;
            Pw[(g + 8) * PSTR + cc + 1] = u3;
        }
        sum0 += __shfl_xor_sync(0xffffffffu, sum0, 1);
        sum0 += __shfl_xor_sync(0xffffffffu, sum0, 2);
        sum1 += __shfl_xor_sync(0xffffffffu, sum1, 1);
        sum1 += __shfl_xor_sync(0xffffffffu, sum1, 2);
        l0 = l0 * al0 + sum0;
        l1 = l1 * al1 + sum1;

        // rescale accumulators
        #pragma unroll
        for (int tn = 0; tn < 16; tn++) {
            accO[tn][0] *= al0; accO[tn][1] *= al0;
            accO[tn][2] *= al1; accO[tn][3] *= al1;
        }

        // V(j) ready
        asm volatile("cp.async.wait_group %0;" :: "n"(2) : "memory");
        __syncthreads();

        // ---- O += P V: warp tile 16 rows x 128 cols, slot (2j+1)%3 ----
        const uint32_t* Vf = (const uint32_t*)(smf + AKV_OFF + ((2 * j + 1) % 3) * SLOT_F);
        #pragma unroll
        for (int ks = 0; ks < 8; ks++) {
            const int k0 = ks * 8;
            uint32_t afr[4], bfr[16][2];
            afr[0] = Pw[g * PSTR + k0 + t];
            afr[1] = Pw[(g + 8) * PSTR + k0 + t];
            afr[2] = Pw[g * PSTR + k0 + t + 4];
            afr[3] = Pw[(g + 8) * PSTR + k0 + t + 4];
            #pragma unroll
            for (int tn = 0; tn < 16; tn++) {
                const int hb = tn * 8 + g;
                bfr[tn][0] = Vf[(k0 + t)     * KVSTR + hb];
                bfr[tn][1] = Vf[(k0 + t + 4) * KVSTR + hb];
            }
            #pragma unroll
            for (int tn = 0; tn < 16; tn++) mma8(accO[tn], afr, bfr[tn]);
        }
    }

    asm volatile("cp.async.wait_group %0;" :: "n"(0) : "memory");

    // epilogue: 1/l scaling + fused sigmoid gate (hybrid exp)
    const int h = n0 + (mW >> 6);
    const int qr0 = qbase + ((mW + g) & 63);
    const int qr1 = qbase + ((mW + g + 8) & 63);
    const float inv0 = 1.0f / l0;
    const float inv1 = 1.0f / l1;
    #pragma unroll
    for (int tn = 0; tn < 16; tn++) {
        const int cc = tn * 8 + 2 * t;
        float2 gg0 = *(const float2*)&qg[qr0 * (NH * 256) + h * 256 + 128 + cc];
        float2 gg1 = *(const float2*)&qg[qr1 * (NH * 256) + h * 256 + 128 + cc];
        float e00, e01, e10, e11;
        if (tn & 1) {
            e00 = exp_poly(-gg0.x); e01 = exp_poly(-gg0.y);
            e10 = exp_poly(-gg1.x); e11 = exp_poly(-gg1.y);
        } else {
            e00 = __expf(-gg0.x); e01 = __expf(-gg0.y);
            e10 = __expf(-gg1.x); e11 = __expf(-gg1.y);
        }
        float s00 = 1.0f / (1.0f + e00);
        float s01 = 1.0f / (1.0f + e01);
        float s10 = 1.0f / (1.0f + e10);
        float s11 = 1.0f / (1.0f + e11);
        float* d0 = enc + qr0 * (NH * HD) + h * HD + cc;
        float* d1 = enc + qr1 * (NH * HD) + h * HD + cc;
        *(float2*)d0 = make_float2(accO[tn][0] * inv0 * s00, accO[tn][1] * inv0 * s01);
        *(float2*)d1 = make_float2(accO[tn][2] * inv1 * s10, accO[tn][3] * inv1 * s11);
    }
}

// ---------------------------------------------------------------------------
extern "C" void kernel_launch(void* const* d_in, const int* in_sizes, int n_in,
                              void* d_out, int out_size)
{
    const float* x0    = (const float*)d_in[0];
    const float* x1    = (const float*)d_in[1];
    const int*   pos   = (const int*)d_in[2];
    const float* qg_w0 = (const float*)d_in[4];
    const float* k_w0  = (const float*)d_in[5];
    const float* v_w0  = (const float*)d_in[6];
    const float* qn0   = (const float*)d_in[7];
    const float* kn0   = (const float*)d_in[8];
    const float* o_w0  = (const float*)d_in[9];
    const float* qg_w1 = (const float*)d_in[10];
    const float* k_w1  = (const float*)d_in[11];
    const float* v_w1  = (const float*)d_in[12];
    const float* qn1   = (const float*)d_in[13];
    const float* kn1   = (const float*)d_in[14];
    const float* o_w1  = (const float*)d_in[15];

    float* out = (float*)d_out;

    float *qg, *kraw, *q, *enc, *ktf, *vtf;
    cudaGetSymbolAddress((void**)&qg,   g_qg);
    cudaGetSymbolAddress((void**)&kraw, g_kraw);
    cudaGetSymbolAddress((void**)&q,    g_q);
    cudaGetSymbolAddress((void**)&enc,  g_enc);
    cudaGetSymbolAddress((void**)&ktf,  g_ktf);
    cudaGetSymbolAddress((void**)&vtf,  g_vtf);

    cudaFuncSetAttribute(proj_fused_kernel, cudaFuncAttributeMaxDynamicSharedMemorySize, GEMM_SMEM_BYTES);
    cudaFuncSetAttribute(proj_out_kernel,   cudaFuncAttributeMaxDynamicSharedMemorySize, GEMM_SMEM_BYTES);
    cudaFuncSetAttribute(attn_kernel, cudaFuncAttributeMaxDynamicSharedMemorySize,
                         ATT_SMEM_F * sizeof(float));

    // all projections in one launch (V dual-written: exact -> d_out, tf32 -> scratch)
    proj_fused_kernel<<<dim3(16, 40), 256, GEMM_SMEM_BYTES>>>(
        x0, x1, qg_w0, qg_w1, k_w0, k_w1, v_w0, v_w1, qg, kraw, out + VC_BASE, vtf);

    // norms + rope (K dual-written; Q pre-rounded to tf32)
    qnorm_rope<<<TT*NH/4, 128>>>(qg, q, pos, qn0, qn1);
    knorm_rope<<<TT*KH/4, 128>>>(kraw, out + KC_BASE, ktf, pos, kn0, kn1);

    // attention: FA2-style register softmax, 2 GQA heads per CTA, fused gate
    attn_kernel<<<dim3(TT/64, NH/2), 256, ATT_SMEM_F * sizeof(float)>>>(
        q, ktf, vtf, qg, enc);

    // output projection
    proj_out_kernel<<<dim3(16, 16), 256, GEMM_SMEM_BYTES>>>(enc, o_w0, o_w1, out);
}

// round 11
// speedup vs baseline: 1.0819x; 1.0359x over previous
#include <cuda_runtime.h>
#include <cuda_bf16.h>
#include <math.h>
#include <stdint.h>

// Problem constants
#define T0 512
#define TT 2048
#define WIDTH 2048
#define NH 16
#define KH 4
#define HD 128
#define KC_BASE (TT*WIDTH)
#define VC_BASE (KC_BASE + TT*KH*HD)
#define NEGV -2.3819763e38f

// Scratch
__device__ float g_qg[TT * NH * 256];
__device__ float g_kraw[TT * KH * HD];
__device__ float g_q[TT * NH * HD];     // tf32-rounded q
__device__ float g_ktf[TT * KH * HD];   // tf32-rounded roped K
__device__ float g_vtf[TT * KH * HD];   // tf32-rounded V
__device__ float g_enc[TT * NH * HD];

// ---------------------------------------------------------------------------
// helpers
// ---------------------------------------------------------------------------
__device__ __forceinline__ uint32_t f2tf(float f) {
    uint32_t r;
    asm("cvt.rna.tf32.f32 %0, %1;" : "=r"(r) : "f"(f));
    return r;
}

__device__ __forceinline__ uint32_t smem_u32(const void* p) {
    uint32_t a;
    asm("{ .reg .u64 t; cvta.to.shared.u64 t, %1; cvt.u32.u64 %0, t; }"
        : "=r"(a) : "l"(p));
    return a;
}

__device__ __forceinline__ void cpasync16(uint32_t s, const float* g) {
    asm volatile("cp.async.ca.shared.global [%0], [%1], 16;" :: "r"(s), "l"(g));
}

// m16n8k8 tf32 MMA, fp32 accumulate.
__device__ __forceinline__ void mma8(float* c, const uint32_t* a, const uint32_t* b) {
    asm volatile(
        "mma.sync.aligned.m16n8k8.row.col.f32.tf32.tf32.f32 "
        "{%0,%1,%2,%3},{%4,%5,%6,%7},{%8,%9},{%0,%1,%2,%3};"
        : "+f"(c[0]), "+f"(c[1]), "+f"(c[2]), "+f"(c[3])
        : "r"(a[0]), "r"(a[1]), "r"(a[2]), "r"(a[3]), "r"(b[0]), "r"(b[1]));
}

// FMA-pipe exp (exp2 poly, |rel err| ~4e-5 << tf32 quantization).
__device__ __forceinline__ float exp_poly(float x) {
    float xl = x * 1.4426950408889634f;
    xl = fmaxf(fminf(xl, 125.0f), -125.0f);
    float nf = rintf(xl);
    float fr = xl - nf;
    float t = fmaf(0.0096183425f, fr, 0.055503327f);
    t = fmaf(t, fr, 0.24022651f);
    t = fmaf(t, fr, 0.69314718f);
    t = fmaf(t, fr, 1.0f);
    return __uint_as_float(__float_as_uint(t) + (int)nf * 8388608);
}

// ---------------------------------------------------------------------------
// cp.async pipelined tf32 GEMM core. Optional second (tf32-rounded) output.
// ---------------------------------------------------------------------------
#define ASTRF 20
#define BSTRF 136
#define A_STAGE (128 * ASTRF)
#define B_STAGE (16 * BSTRF)
#define STAGE_F (A_STAGE + B_STAGE)
#define GEMM_SMEM_BYTES (3 * STAGE_F * 4)

__device__ __forceinline__ void issue_stage(
    uint32_t sbase, int stage, const float* A, int lda,
    const float* B, int ldb, int k0, int tid)
{
    const uint32_t aS = sbase + stage * (STAGE_F * 4);
    const uint32_t bS = aS + A_STAGE * 4;
    const int ar = tid >> 2, ak = (tid & 3) * 4;
    const int br = tid >> 5, bc = (tid & 31) * 4;
    cpasync16(aS + (ar * ASTRF + ak) * 4,          A + (long)ar * lda + k0 + ak);
    cpasync16(aS + ((64 + ar) * ASTRF + ak) * 4,   A + (long)(64 + ar) * lda + k0 + ak);
    cpasync16(bS + (br * BSTRF + bc) * 4,          B + (long)(k0 + br) * ldb + bc);
    cpasync16(bS + ((8 + br) * BSTRF + bc) * 4,    B + (long)(k0 + 8 + br) * ldb + bc);
    asm volatile("cp.async.commit_group;" ::: "memory");
}

__device__ void gemm_async_core(
    const float* __restrict__ A, int lda,
    const float* __restrict__ B, int ldb,
    float* __restrict__ C, float* __restrict__ C2, int ldc, int Kdim)
{
    extern __shared__ float smf[];
    const uint32_t sbase = smem_u32(smf);

    const int tid = threadIdx.x;
    const int lane = tid & 31;
    const int g = lane >> 2;
    const int t = lane & 3;
    const int wid = tid >> 5;
    const int mw = (wid >> 1) * 32;
    const int nw = (wid & 1) * 64;

    const int nt = Kdim / 16;

    issue_stage(sbase, 0, A, lda, B, ldb, 0, tid);
    issue_stage(sbase, 1, A, lda, B, ldb, 16, tid);

    float acc[2][8][4] = {};

    for (int kt = 0; kt < nt; kt++) {
        if (kt + 2 < nt) {
            issue_stage(sbase, (kt + 2) % 3, A, lda, B, ldb, (kt + 2) * 16, tid);
            asm volatile("cp.async.wait_group %0;" :: "n"(2) : "memory");
        } else if (kt + 1 < nt) {
            asm volatile("cp.async.wait_group %0;" :: "n"(1) : "memory");
        } else {
            asm volatile("cp.async.wait_group %0;" :: "n"(0) : "memory");
        }
        __syncthreads();

        const float* AsF = smf + (kt % 3) * STAGE_F;
        const float* BsF = AsF + A_STAGE;

        #pragma unroll
        for (int h = 0; h < 2; h++) {
            const int k0 = h * 8;
            uint32_t afr[2][4], bfr[8][2];
            #pragma unroll
            for (int tm = 0; tm < 2; tm++) {
                const int mb = mw + tm * 16;
                afr[tm][0] = f2tf(AsF[(mb + g)     * ASTRF + k0 + t]);
                afr[tm][1] = f2tf(AsF[(mb + g + 8) * ASTRF + k0 + t]);
                afr[tm][2] = f2tf(AsF[(mb + g)     * ASTRF + k0 + t + 4]);
                afr[tm][3] = f2tf(AsF[(mb + g + 8) * ASTRF + k0 + t + 4]);
            }
            #pragma unroll
            for (int tn = 0; tn < 8; tn++) {
                const int nb = nw + tn * 8 + g;
                bfr[tn][0] = f2tf(BsF[(k0 + t)     * BSTRF + nb]);
                bfr[tn][1] = f2tf(BsF[(k0 + t + 4) * BSTRF + nb]);
            }
            #pragma unroll
            for (int tm = 0; tm < 2; tm++)
                #pragma unroll
                for (int tn = 0; tn < 8; tn++)
                    mma8(acc[tm][tn], afr[tm], bfr[tn]);
        }
        __syncthreads();
    }

    #pragma unroll
    for (int tm = 0; tm < 2; tm++) {
        #pragma unroll
        for (int tn = 0; tn < 8; tn++) {
            const int r0 = mw + tm * 16 + g;
            const int cc = nw + tn * 8 + 2 * t;
            *(float2*)&C[r0 * ldc + cc]       = make_float2(acc[tm][tn][0], acc[tm][tn][1]);
            *(float2*)&C[(r0 + 8) * ldc + cc] = make_float2(acc[tm][tn][2], acc[tm][tn][3]);
            if (C2) {
                *(float2*)&C2[r0 * ldc + cc] = make_float2(
                    __uint_as_float(f2tf(acc[tm][tn][0])), __uint_as_float(f2tf(acc[tm][tn][1])));
                *(float2*)&C2[(r0 + 8) * ldc + cc] = make_float2(
                    __uint_as_float(f2tf(acc[tm][tn][2])), __uint_as_float(f2tf(acc[tm][tn][3])));
            }
        }
    }
}

// Fused projections: qg (y 0..31), K (y 32..35), V (y 36..39). grid (16, 40).
__global__ __launch_bounds__(256, 2) void proj_fused_kernel(
    const float* __restrict__ x0, const float* __restrict__ x1,
    const float* __restrict__ qgw0, const float* __restrict__ qgw1,
    const float* __restrict__ kw0, const float* __restrict__ kw1,
    const float* __restrict__ vw0, const float* __restrict__ vw1,
    float* __restrict__ qg, float* __restrict__ kraw,
    float* __restrict__ vcache, float* __restrict__ vtf)
{
    const int tile = blockIdx.x;
    const int y = blockIdx.y;
    const float* A = (tile < 4) ? (x0 + (long)tile * 128 * WIDTH)
                                : (x1 + (long)(tile - 4) * 128 * WIDTH);
    const float* B;
    float* C;
    float* C2 = nullptr;
    int ldb, ldc;
    if (y < 32) {
        const int n = y >> 1, bn = (y & 1) * 128;
        B = ((tile < 4) ? qgw0 : qgw1) + (long)n * WIDTH * 256 + bn;
        ldb = 256;
        C = qg + (long)tile * 128 * (NH * 256) + n * 256 + bn;
        ldc = NH * 256;
    } else if (y < 36) {
        const int kk = y - 32;
        B = ((tile < 4) ? kw0 : kw1) + (long)kk * WIDTH * HD;
        ldb = HD;
        C = kraw + (long)tile * 128 * (KH * HD) + kk * HD;
        ldc = KH * HD;
    } else {
        const int kk = y - 36;
        B = ((tile < 4) ? vw0 : vw1) + (long)kk * WIDTH * HD;
        ldb = HD;
        C = vcache + (long)tile * 128 * (KH * HD) + kk * HD;
        C2 = vtf + (long)tile * 128 * (KH * HD) + kk * HD;
        ldc = KH * HD;
    }
    gemm_async_core(A, WIDTH, B, ldb, C, C2, ldc, WIDTH);
}

// output projection: grid (16, 16)
__global__ __launch_bounds__(256, 2) void proj_out_kernel(
    const float* __restrict__ enc,
    const float* __restrict__ ow0, const float* __restrict__ ow1,
    float* __restrict__ out)
{
    const int tile = blockIdx.x;
    const int bn = blockIdx.y * 128;
    const float* A = enc + (long)tile * 128 * (NH * HD);
    const float* B = ((tile < 4) ? ow0 : ow1) + bn;
    float* C = out + (long)tile * 128 * WIDTH + bn;
    gemm_async_core(A, NH * HD, B, WIDTH, C, nullptr, WIDTH, NH * HD);
}

// ---------------------------------------------------------------------------
// RMSNorm + RoPE
// ---------------------------------------------------------------------------
__global__ __launch_bounds__(128) void qnorm_rope(
    const float* __restrict__ qg, float* __restrict__ qout,
    const int* __restrict__ positions,
    const float* __restrict__ qn0, const float* __restrict__ qn1)
{
    int row  = blockIdx.x * 4 + (threadIdx.x >> 5);
    int lane = threadIdx.x & 31;
    int t = row >> 4;
    int n = row & 15;
    const float* src = qg + t * (NH * 256) + n * 256;

    float v0 = src[lane];
    float v1 = src[lane + 32];
    float v2 = src[lane + 64];
    float v3 = src[lane + 96];
    float ss = v0 * v0 + v1 * v1 + v2 * v2 + v3 * v3;
    #pragma unroll
    for (int o = 16; o; o >>= 1) ss += __shfl_xor_sync(0xffffffffu, ss, o);
    float inv = rsqrtf(ss * (1.0f / 128.0f) + 1e-6f);

    const float* qn = (t < T0) ? qn0 : qn1;
    v0 = v0 * inv * (1.0f + qn[lane]);
    v1 = v1 * inv * (1.0f + qn[lane + 32]);
    v2 = v2 * inv * (1.0f + qn[lane + 64]);
    v3 = v3 * inv * (1.0f + qn[lane + 96]);

    float p = (float)positions[t];
    float freq = powf(1000000.0f, -(float)lane / 32.0f);
    float s, c;
    sincosf(p * freq, &s, &c);

    const float SCL = 0.08838834764831845f;
    float* dst = qout + t * (NH * HD) + n * HD;
    dst[lane]      = __uint_as_float(f2tf((v0 * c - v1 * s) * SCL));
    dst[lane + 32] = __uint_as_float(f2tf((v1 * c + v0 * s) * SCL));
    dst[lane + 64] = __uint_as_float(f2tf(v2 * SCL));
    dst[lane + 96] = __uint_as_float(f2tf(v3 * SCL));
}

__global__ __launch_bounds__(128) void knorm_rope(
    const float* __restrict__ kraw, float* __restrict__ kcache,
    float* __restrict__ ktf,
    const int* __restrict__ positions,
    const float* __restrict__ kn0, const float* __restrict__ kn1)
{
    int row  = blockIdx.x * 4 + (threadIdx.x >> 5);
    int lane = threadIdx.x & 31;
    int t  = row >> 2;
    int kk = row & 3;
    const float* src = kraw + t * (KH * HD) + kk * HD;

    float v0 = src[lane];
    float v1 = src[lane + 32];
    float v2 = src[lane + 64];
    float v3 = src[lane + 96];
    float ss = v0 * v0 + v1 * v1 + v2 * v2 + v3 * v3;
    #pragma unroll
    for (int o = 16; o; o >>= 1) ss += __shfl_xor_sync(0xffffffffu, ss, o);
    float inv = rsqrtf(ss * (1.0f / 128.0f) + 1e-6f);

    const float* kn = (t < T0) ? kn0 : kn1;
    v0 = v0 * inv * (1.0f + kn[lane]);
    v1 = v1 * inv * (1.0f + kn[lane + 32]);
    v2 = v2 * inv * (1.0f + kn[lane + 64]);
    v3 = v3 * inv * (1.0f + kn[lane + 96]);

    float p = (float)positions[t];
    float freq = powf(1000000.0f, -(float)lane / 32.0f);
    float s, c;
    sincosf(p * freq, &s, &c);

    float r0 = v0 * c - v1 * s;
    float r1 = v1 * c + v0 * s;

    float* dst = kcache + t * (KH * HD) + kk * HD;
    dst[lane]      = r0;
    dst[lane + 32] = r1;
    dst[lane + 64] = v2;
    dst[lane + 96] = v3;

    float* dtf = ktf + t * (KH * HD) + kk * HD;
    dtf[lane]      = __uint_as_float(f2tf(r0));
    dtf[lane + 32] = __uint_as_float(f2tf(r1));
    dtf[lane + 64] = __uint_as_float(f2tf(v2));
    dtf[lane + 96] = __uint_as_float(f2tf(v3));
}

// ---------------------------------------------------------------------------
// Flash attention: 1 head x 64 queries per CTA, 128 threads (4 warps),
// 2 CTAs/SM. Q in REGISTERS. XOR-swizzled unpadded K/V slots (3-slot
// rotation) + warp-private swizzled P. FA2 register softmax, 3 barriers/iter.
// smem: 3 x (64x128) KV + 4 x (16x64) P = 112 KB exactly.
// ---------------------------------------------------------------------------
#define SLOT_F (64 * 128)
#define AP_OFF (3 * SLOT_F)
#define ATT_SMEM_F (AP_OFF + 4 * 16 * 64)   // 28672 floats = 114688 B = 112 KB

// 16B-chunk swizzle for 64-row x 128-col tile (32 chunks/row)
#define SWG(r, c16) ((r) * 32 + ((c16) ^ ((r) & 7)))
// 16B-chunk swizzle for 16-row x 64-col P tile (16 chunks/row)
#define SWP(r, gq) ((r) * 16 + ((gq) ^ ((r) & 7)))

__device__ __forceinline__ void att_issue(
    uint32_t kvbase, int slot, const float* __restrict__ src, int sb, int tid)
{
    const uint32_t dst = kvbase + slot * (SLOT_F * 4);
    #pragma unroll
    for (int i = 0; i < 16; i++) {
        const int lin = tid + 128 * i;
        const int r = lin >> 5;
        const int c16 = lin & 31;
        cpasync16(dst + SWG(r, c16) * 16, src + (long)(sb + r) * (KH * HD) + c16 * 4);
    }
    asm volatile("cp.async.commit_group;" ::: "memory");
}

__global__ __launch_bounds__(128, 2) void attn_kernel(
    const float* __restrict__ q, const float* __restrict__ ktf,
    const float* __restrict__ vtf, const float* __restrict__ qg,
    float* __restrict__ enc)
{
    extern __shared__ float smf[];
    const uint32_t kvbase = smem_u32(smf);

    const int tid = threadIdx.x;
    const int lane = tid & 31;
    const int g = lane >> 2;
    const int t = lane & 3;
    const int wid = tid >> 5;                    // 0..3
    const int mW = wid * 16;                     // warp row base (0..48)
    const int qt = gridDim.x - 1 - blockIdx.x;   // heavy tiles first
    const int n = blockIdx.y;                    // head
    const int kvh = n >> 2;
    const int qbase = qt * 64;

    uint32_t* Pw = (uint32_t*)(smf + AP_OFF) + wid * (16 * 64);

    const float* kbase = ktf + kvh * HD;
    const float* vbase = vtf + kvh * HD;

    // ---- stage Q into slot 2, then pull fragments into registers ----
    {
        const uint32_t qdst = kvbase + 2 * (SLOT_F * 4);
        #pragma unroll
        for (int i = 0; i < 16; i++) {
            const int lin = tid + 128 * i;
            const int r = lin >> 5;
            const int c16 = lin & 31;
            cpasync16(qdst + SWG(r, c16) * 16,
                      q + (long)(qbase + r) * (NH * HD) + n * HD + c16 * 4);
        }
        asm volatile("cp.async.commit_group;" ::: "memory");
        asm volatile("cp.async.wait_group 0;" ::: "memory");
        __syncthreads();
    }
    uint32_t qreg[16][4];
    {
        const uint32_t* Qs = (const uint32_t*)(smf + 2 * SLOT_F);
        #pragma unroll
        for (int ks = 0; ks < 16; ks++) {
            qreg[ks][0] = Qs[SWG(mW + g,     2 * ks) * 4 + t];
            qreg[ks][1] = Qs[SWG(mW + g + 8, 2 * ks) * 4 + t];
            qreg[ks][2] = Qs[SWG(mW + g,     2 * ks + 1) * 4 + t];
            qreg[ks][3] = Qs[SWG(mW + g + 8, 2 * ks + 1) * 4 + t];
        }
    }
    __syncthreads();

    // kick off K(0) -> slot0, V(0) -> slot1
    att_issue(kvbase, 0, kbase, 0, tid);
    att_issue(kvbase, 1, vbase, 0, tid);

    float m0 = -3.0e38f, m1 = -3.0e38f, l0 = 0.0f, l1 = 0.0f;
    float accO[16][4] = {};

    for (int j = 0; j <= qt; j++) {
        const int nsb = (j + 1 <= qt) ? (j + 1) * 64 : qt * 64;

        // K(j) ready (V(j) may still be in flight)
        asm volatile("cp.async.wait_group %0;" :: "n"(1) : "memory");
        __syncthreads();

        att_issue(kvbase, (2 * j + 2) % 3, kbase, nsb, tid);

        // ---- S = Q K^T: 16 rows x 64 keys, slot (2j)%3, Q from regs ----
        const uint32_t* Kf = (const uint32_t*)(smf + ((2 * j) % 3) * SLOT_F);
        float sacc[8][4] = {};
        #pragma unroll
        for (int ks = 0; ks < 16; ks++) {
            uint32_t bfr[8][2];
            #pragma unroll
            for (int tn = 0; tn < 8; tn++) {
                const int key = tn * 8 + g;
                bfr[tn][0] = Kf[SWG(key, 2 * ks) * 4 + t];
                bfr[tn][1] = Kf[SWG(key, 2 * ks + 1) * 4 + t];
            }
            #pragma unroll
            for (int tn = 0; tn < 8; tn++) mma8(sacc[tn], qreg[ks], bfr[tn]);
        }
        __syncthreads();   // all warps done reading K(j); slot free

        att_issue(kvbase, (2 * j) % 3, vbase, nsb, tid);

        // ---- causal mask + register online softmax ----
        const int q0 = mW + g, q1 = mW + g + 8;
        if (j == qt) {
            #pragma unroll
            for (int tn = 0; tn < 8; tn++) {
                const int cc = tn * 8 + 2 * t;
                if (cc     > q0) sacc[tn][0] = NEGV;
                if (cc + 1 > q0) sacc[tn][1] = NEGV;
                if (cc     > q1) sacc[tn][2] = NEGV;
                if (cc + 1 > q1) sacc[tn][3] = NEGV;
            }
        }
        float rmax0 = -3.0e38f, rmax1 = -3.0e38f;
        #pragma unroll
        for (int tn = 0; tn < 8; tn++) {
            rmax0 = fmaxf(rmax0, fmaxf(sacc[tn][0], sacc[tn][1]));
            rmax1 = fmaxf(rmax1, fmaxf(sacc[tn][2], sacc[tn][3]));
        }
        rmax0 = fmaxf(rmax0, __shfl_xor_sync(0xffffffffu, rmax0, 1));
        rmax0 = fmaxf(rmax0, __shfl_xor_sync(0xffffffffu, rmax0, 2));
        rmax1 = fmaxf(rmax1, __shfl_xor_sync(0xffffffffu, rmax1, 1));
        rmax1 = fmaxf(rmax1, __shfl_xor_sync(0xffffffffu, rmax1, 2));
        const float mn0 = fmaxf(m0, rmax0);
        const float mn1 = fmaxf(m1, rmax1);
        const float al0 = __expf(m0 - mn0);
        const float al1 = __expf(m1 - mn1);
        m0 = mn0; m1 = mn1;

        float sum0 = 0.0f, sum1 = 0.0f;
        #pragma unroll
        for (int tn = 0; tn < 8; tn++) {
            float p0, p1, p2, p3;
            if (tn & 1) {
                p0 = exp_poly(sacc[tn][0] - mn0); p1 = exp_poly(sacc[tn][1] - mn0);
                p2 = exp_poly(sacc[tn][2] - mn1); p3 = exp_poly(sacc[tn][3] - mn1);
            } else {
                p0 = __expf(sacc[tn][0] - mn0); p1 = __expf(sacc[tn][1] - mn0);
                p2 = __expf(sacc[tn][2] - mn1); p3 = __expf(sacc[tn][3] - mn1);
            }
            sum0 += p0 + p1;
            sum1 += p2 + p3;
            // write P tf32 into warp-private swizzled smem (no barrier needed)
            const int pg = 2 * tn + (t >> 1);
            const int pw = (2 * t) & 3;
            const int i0 = SWP(g, pg) * 4 + pw;
            const int i1 = SWP(g + 8, pg) * 4 + pw;
            Pw[i0]     = f2tf(p0);
            Pw[i0 + 1] = f2tf(p1);
            Pw[i1]     = f2tf(p2);
            Pw[i1 + 1] = f2tf(p3);
        }
        sum0 += __shfl_xor_sync(0xffffffffu, sum0, 1);
        sum0 += __shfl_xor_sync(0xffffffffu, sum0, 2);
        sum1 += __shfl_xor_sync(0xffffffffu, sum1, 1);
        sum1 += __shfl_xor_sync(0xffffffffu, sum1, 2);
        l0 = l0 * al0 + sum0;
        l1 = l1 * al1 + sum1;

        #pragma unroll
        for (int tn = 0; tn < 16; tn++) {
            accO[tn][0] *= al0; accO[tn][1] *= al0;
            accO[tn][2] *= al1; accO[tn][3] *= al1;
        }

        // V(j) ready
        asm volatile("cp.async.wait_group %0;" :: "n"(2) : "memory");
        __syncthreads();

        // ---- O += P V: 16 rows x 128 cols, slot (2j+1)%3 ----
        const uint32_t* Vf = (const uint32_t*)(smf + ((2 * j + 1) % 3) * SLOT_F);
        #pragma unroll
        for (int ks = 0; ks < 8; ks++) {
            uint32_t afr[4], bfr[16][2];
            afr[0] = Pw[SWP(g,     2 * ks) * 4 + t];
            afr[1] = Pw[SWP(g + 8, 2 * ks) * 4 + t];
            afr[2] = Pw[SWP(g,     2 * ks + 1) * 4 + t];
            afr[3] = Pw[SWP(g + 8, 2 * ks + 1) * 4 + t];
            const int k0 = ks * 8;
            #pragma unroll
            for (int tn = 0; tn < 16; tn++) {
                const int vg = 2 * tn + (g >> 2);
                const int vw = g & 3;
                bfr[tn][0] = Vf[SWG(k0 + t,     vg) * 4 + vw];
                bfr[tn][1] = Vf[SWG(k0 + t + 4, vg) * 4 + vw];
            }
            #pragma unroll
            for (int tn = 0; tn < 16; tn++) mma8(accO[tn], afr, bfr[tn]);
        }
    }

    asm volatile("cp.async.wait_group %0;" :: "n"(0) : "memory");

    // epilogue: 1/l scaling + fused sigmoid gate (hybrid exp)
    const int qr0 = qbase + mW + g;
    const int qr1 = qr0 + 8;
    const float inv0 = 1.0f / l0;
    const float inv1 = 1.0f / l1;
    #pragma unroll
    for (int tn = 0; tn < 16; tn++) {
        const int cc = tn * 8 + 2 * t;
        float2 gg0 = *(const float2*)&qg[qr0 * (NH * 256) + n * 256 + 128 + cc];
        float2 gg1 = *(const float2*)&qg[qr1 * (NH * 256) + n * 256 + 128 + cc];
        float e00, e01, e10, e11;
        if (tn & 1) {
            e00 = exp_poly(-gg0.x); e01 = exp_poly(-gg0.y);
            e10 = exp_poly(-gg1.x); e11 = exp_poly(-gg1.y);
        } else {
            e00 = __expf(-gg0.x); e01 = __expf(-gg0.y);
            e10 = __expf(-gg1.x); e11 = __expf(-gg1.y);
        }
        float s00 = 1.0f / (1.0f + e00);
        float s01 = 1.0f / (1.0f + e01);
        float s10 = 1.0f / (1.0f + e10);
        float s11 = 1.0f / (1.0f + e11);
        float* d0 = enc + qr0 * (NH * HD) + n * HD + cc;
        float* d1 = enc + qr1 * (NH * HD) + n * HD + cc;
        *(float2*)d0 = make_float2(accO[tn][0] * inv0 * s00, accO[tn][1] * inv0 * s01);
        *(float2*)d1 = make_float2(accO[tn][2] * inv1 * s10, accO[tn][3] * inv1 * s11);
    }
}

// ---------------------------------------------------------------------------
extern "C" void kernel_launch(void* const* d_in, const int* in_sizes, int n_in,
                              void* d_out, int out_size)
{
    const float* x0    = (const float*)d_in[0];
    const float* x1    = (const float*)d_in[1];
    const int*   pos   = (const int*)d_in[2];
    const float* qg_w0 = (const float*)d_in[4];
    const float* k_w0  = (const float*)d_in[5];
    const float* v_w0  = (const float*)d_in[6];
    const float* qn0   = (const float*)d_in[7];
    const float* kn0   = (const float*)d_in[8];
    const float* o_w0  = (const float*)d_in[9];
    const float* qg_w1 = (const float*)d_in[10];
    const float* k_w1  = (const float*)d_in[11];
    const float* v_w1  = (const float*)d_in[12];
    const float* qn1   = (const float*)d_in[13];
    const float* kn1   = (const float*)d_in[14];
    const float* o_w1  = (const float*)d_in[15];

    float* out = (float*)d_out;

    float *qg, *kraw, *q, *enc, *ktf, *vtf;
    cudaGetSymbolAddress((void**)&qg,   g_qg);
    cudaGetSymbolAddress((void**)&kraw, g_kraw);
    cudaGetSymbolAddress((void**)&q,    g_q);
    cudaGetSymbolAddress((void**)&enc,  g_enc);
    cudaGetSymbolAddress((void**)&ktf,  g_ktf);
    cudaGetSymbolAddress((void**)&vtf,  g_vtf);

    cudaFuncSetAttribute(proj_fused_kernel, cudaFuncAttributeMaxDynamicSharedMemorySize, GEMM_SMEM_BYTES);
    cudaFuncSetAttribute(proj_out_kernel,   cudaFuncAttributeMaxDynamicSharedMemorySize, GEMM_SMEM_BYTES);
    cudaFuncSetAttribute(attn_kernel, cudaFuncAttributeMaxDynamicSharedMemorySize,
                         ATT_SMEM_F * sizeof(float));

    // all projections in one launch (V dual-written: exact -> d_out, tf32 -> scratch)
    proj_fused_kernel<<<dim3(16, 40), 256, GEMM_SMEM_BYTES>>>(
        x0, x1, qg_w0, qg_w1, k_w0, k_w1, v_w0, v_w1, qg, kraw, out + VC_BASE, vtf);

    // norms + rope (K dual-written; Q pre-rounded to tf32)
    qnorm_rope<<<TT*NH/4, 128>>>(qg, q, pos, qn0, qn1);
    knorm_rope<<<TT*KH/4, 128>>>(kraw, out + KC_BASE, ktf, pos, kn0, kn1);

    // attention: 1 head per CTA, Q in regs, 2 CTAs/SM, fused gate
    attn_kernel<<<dim3(TT/64, NH), 128, ATT_SMEM_F * sizeof(float)>>>(
        q, ktf, vtf, qg, enc);

    // output projection
    proj_out_kernel<<<dim3(16, 16), 256, GEMM_SMEM_BYTES>>>(enc, o_w0, o_w1, out);
}